// round 10
// baseline (speedup 1.0000x reference)
#include <cuda_runtime.h>
#include <cuda_bf16.h>
#include <math.h>

#define D        32
#define TSPLIT   8
#define NTT      64            // train per tile
#define MQ       128           // queries per CTA
#define M_MAX    16384
#define N_MAX    8192
#define EPSV     1e-8f
#define BWB      64
#define SCQ      65024.0f      // fixed-point scale

// smem: pitch-48 rows (conflict-free ldmatrix). Buf: B1[0,3072) B0[3072,6144) ext[6144,6656)
#define PITCH    48
#define BREG     3072
#define BUFSZ    6656
#define SMEMSZ   13312         // 2 bufs; A staging (2*6144=12288) aliases

__device__ float        g_cl;
__device__ char         g_A1[M_MAX * D];    // query hi int8
__device__ char         g_A0[M_MAX * D];    // query lo int8
__device__ char         g_B1[N_MAX * D];    // train hi int8
__device__ char         g_B0[N_MAX * D];    // train lo int8
__device__ float4       g_ext4[N_MAX / 2];  // {Ct_even, Ct_odd, r_even, r_odd}
__device__ float        g_qe[M_MAX];        // Cq
__device__ double       g_bws [BWB * D];
__device__ double       g_bws2[BWB * D];
__device__ float        g_pnd[M_MAX][TSPLIT * 2];  // [q][s*2]=num, [q][s*2+1]=den
__device__ float        g_rx[M_MAX];
__device__ unsigned int g_rmin, g_rmax, g_smin, g_smax;

// ---------------- helpers ----------------
__device__ __forceinline__ unsigned long long pack2(float lo, float hi) {
    unsigned long long r; asm("mov.b64 %0, {%1, %2};" : "=l"(r) : "f"(lo), "f"(hi)); return r;
}
__device__ __forceinline__ unsigned long long dup2(float v) {
    unsigned long long r; asm("mov.b64 %0, {%1, %1};" : "=l"(r) : "f"(v)); return r;
}
__device__ __forceinline__ unsigned long long fma2(unsigned long long a, unsigned long long b, unsigned long long c) {
    unsigned long long d; asm("fma.rn.f32x2 %0, %1, %2, %3;" : "=l"(d) : "l"(a), "l"(b), "l"(c)); return d;
}
__device__ __forceinline__ unsigned long long add2(unsigned long long a, unsigned long long b) {
    unsigned long long d; asm("add.rn.f32x2 %0, %1, %2;" : "=l"(d) : "l"(a), "l"(b)); return d;
}
__device__ __forceinline__ float2 unpack2(unsigned long long p) {
    float2 f; asm("mov.b64 {%0, %1}, %2;" : "=f"(f.x), "=f"(f.y) : "l"(p)); return f;
}
__device__ __forceinline__ float ex2f(float a) {
    float r; asm("ex2.approx.f32 %0, %1;" : "=f"(r) : "f"(a)); return r;
}
__device__ __forceinline__ void cp16(unsigned dst, const void* src) {
    asm volatile("cp.async.ca.shared.global [%0], [%1], 16;" :: "r"(dst), "l"(src));
}
__device__ __forceinline__ unsigned fenc(float f) {
    unsigned u = __float_as_uint(f); return (u & 0x80000000u) ? ~u : (u | 0x80000000u);
}
__device__ __forceinline__ float fdec(unsigned u) {
    u = (u & 0x80000000u) ? (u & 0x7fffffffu) : ~u; return __uint_as_float(u);
}
__device__ __forceinline__ float warp_min(float v) {
    #pragma unroll
    for (int o = 16; o; o >>= 1) v = fminf(v, __shfl_xor_sync(~0u, v, o));
    return v;
}
__device__ __forceinline__ float warp_max(float v) {
    #pragma unroll
    for (int o = 16; o; o >>= 1) v = fmaxf(v, __shfl_xor_sync(~0u, v, o));
    return v;
}
__device__ __forceinline__ void ldmx4(unsigned* r, unsigned addr) {
    asm volatile("ldmatrix.sync.aligned.m8n8.x4.shared.b16 {%0,%1,%2,%3}, [%4];"
                 : "=r"(r[0]), "=r"(r[1]), "=r"(r[2]), "=r"(r[3]) : "r"(addr));
}
__device__ __forceinline__ void mma_s8(int* c, const unsigned* a, unsigned b0, unsigned b1) {
    asm volatile("mma.sync.aligned.m16n8k32.row.col.s32.s8.s8.s32 "
                 "{%0,%1,%2,%3}, {%4,%5,%6,%7}, {%8,%9}, {%0,%1,%2,%3};"
                 : "+r"(c[0]), "+r"(c[1]), "+r"(c[2]), "+r"(c[3])
                 : "r"(a[0]), "r"(a[1]), "r"(a[2]), "r"(a[3]), "r"(b0), "r"(b1));
}
// split p in [-0.5,0.5] into (hi,lo) int8 pair; P = hi*256+lo
__device__ __forceinline__ void qsplit(float p, int& hi, int& lo) {
    int P = __float2int_rn(p * SCQ);
    hi = (P + 128) >> 8;
    lo = P - (hi << 8);
}

// ---------------- bandwidth ----------------
__global__ void k_bw1(const float* __restrict__ tx) {
    __shared__ double sds[8][8][4], sds2[8][8][4];
    const int tid = threadIdx.x, b = blockIdx.x;
    const float4* tx4 = (const float4*)tx;
    double s[4] = {0,0,0,0}, s2[4] = {0,0,0,0};
    #pragma unroll
    for (int it = 0; it < 4; it++) {
        float4 v = tx4[(size_t)(b * 128 + it * 32) * 8 + tid];
        double vx = v.x, vy = v.y, vz = v.z, vw = v.w;
        s[0] += vx; s2[0] += vx*vx; s[1] += vy; s2[1] += vy*vy;
        s[2] += vz; s2[2] += vz*vz; s[3] += vw; s2[3] += vw*vw;
    }
    #pragma unroll
    for (int o = 8; o <= 16; o <<= 1)
        #pragma unroll
        for (int k = 0; k < 4; k++) {
            s[k]  += __shfl_xor_sync(~0u, s[k],  o);
            s2[k] += __shfl_xor_sync(~0u, s2[k], o);
        }
    int w = tid >> 5, l = tid & 31;
    if (l < 8)
        #pragma unroll
        for (int k = 0; k < 4; k++) { sds[w][l][k] = s[k]; sds2[w][l][k] = s2[k]; }
    __syncthreads();
    if (tid < 8)
        #pragma unroll
        for (int k = 0; k < 4; k++) {
            double a = 0, a2 = 0;
            #pragma unroll
            for (int ww = 0; ww < 8; ww++) { a += sds[ww][tid][k]; a2 += sds2[ww][tid][k]; }
            g_bws[b * D + tid * 4 + k] = a; g_bws2[b * D + tid * 4 + k] = a2;
        }
}
__global__ void k_bw2(int n) {
    int d = threadIdx.x;
    double s = 0, s2 = 0;
    for (int b = 0; b < BWB; b++) { s += g_bws[b * D + d]; s2 += g_bws2[b * D + d]; }
    double mean = s / n, var = (s2 - n * mean * mean) / (n - 1);
    double sd = sqrt(var > 0.0 ? var : 0.0);
    #pragma unroll
    for (int o = 16; o; o >>= 1) sd += __shfl_xor_sync(~0u, sd, o);
    if (d == 0) {
        double bw = (sd / D) * exp(-log((double)n) / (D + 4));
        g_cl = (float)(1.0 / (2.0 * bw * bw) * 1.4426950408889634);
        g_rmin = ~0u; g_rmax = 0u; g_smin = ~0u; g_smax = 0u;
    }
}

// ---------------- coalesced prep: 8 threads per row ----------------
__global__ void k_qprep(const float* __restrict__ x, int m) {
    int idx = blockIdx.x * 256 + threadIdx.x;
    int row = idx >> 3, g = idx & 7;
    float4 v = ((const float4*)x)[(size_t)row * 8 + g];
    float q2 = fmaf(v.x, v.x, fmaf(v.y, v.y, fmaf(v.z, v.z, v.w * v.w)));
    float px = v.x - 0.5f, py = v.y - 0.5f, pz = v.z - 0.5f, pw = v.w - 0.5f;
    float sp = px + py + pz + pw;
    #pragma unroll
    for (int o = 1; o <= 4; o <<= 1) {
        q2 += __shfl_xor_sync(~0u, q2, o);
        sp += __shfl_xor_sync(~0u, sp, o);
    }
    int h0, l0, h1, l1, h2, l2, h3, l3;
    qsplit(px, h0, l0); qsplit(py, h1, l1);
    qsplit(pz, h2, l2); qsplit(pw, h3, l3);
    unsigned hw = (h0 & 255) | ((h1 & 255) << 8) | ((h2 & 255) << 16) | ((h3 & 255) << 24);
    unsigned lw = (l0 & 255) | ((l1 & 255) << 8) | ((l2 & 255) << 16) | ((l3 & 255) << 24);
    ((unsigned*)g_A1)[(size_t)row * 8 + g] = hw;
    ((unsigned*)g_A0)[(size_t)row * 8 + g] = lw;
    if (g == 0) {
        float cl = g_cl, K2 = cl + cl;
        g_qe[row] = 0.5f * K2 * sp - cl * q2 + 8.0f * K2;
    }
}
__global__ void k_tprep(const float* __restrict__ tx, const float* __restrict__ tr, int n) {
    int idx = blockIdx.x * 256 + threadIdx.x;
    int row = idx >> 3, g = idx & 7;
    float4 v = ((const float4*)tx)[(size_t)row * 8 + g];
    float t2 = fmaf(v.x, v.x, fmaf(v.y, v.y, fmaf(v.z, v.z, v.w * v.w)));
    float px = v.x - 0.5f, py = v.y - 0.5f, pz = v.z - 0.5f, pw = v.w - 0.5f;
    float sp = px + py + pz + pw;
    #pragma unroll
    for (int o = 1; o <= 4; o <<= 1) {
        t2 += __shfl_xor_sync(~0u, t2, o);
        sp += __shfl_xor_sync(~0u, sp, o);
    }
    int h0, l0, h1, l1, h2, l2, h3, l3;
    qsplit(px, h0, l0); qsplit(py, h1, l1);
    qsplit(pz, h2, l2); qsplit(pw, h3, l3);
    unsigned hw = (h0 & 255) | ((h1 & 255) << 8) | ((h2 & 255) << 16) | ((h3 & 255) << 24);
    unsigned lw = (l0 & 255) | ((l1 & 255) << 8) | ((l2 & 255) << 16) | ((l3 & 255) << 24);
    ((unsigned*)g_B1)[(size_t)row * 8 + g] = hw;
    ((unsigned*)g_B0)[(size_t)row * 8 + g] = lw;
    if (g == 0) {
        float cl = g_cl, K2 = cl + cl;
        float ct = 0.5f * K2 * sp - cl * t2;
        float* e = (float*)&g_ext4[row >> 1];
        if (row & 1) { e[1] = ct; e[3] = tr[row]; }
        else         { e[0] = ct; e[2] = tr[row]; }
    }
}

// ---------------- IMMA KDE mainloop ----------------
__device__ __forceinline__ void load_tile(unsigned sb, int g, int b, int tid) {
    unsigned base = sb + b * BUFSZ;
    if (tid < 128) {
        int row = tid >> 1, c = tid & 1;
        cp16(base + row * PITCH + c * 16, g_B1 + (size_t)g * NTT * D + row * 32 + c * 16);
    } else {
        int t = tid - 128, row = t >> 1, c = t & 1;
        cp16(base + BREG + row * PITCH + c * 16, g_B0 + (size_t)g * NTT * D + row * 32 + c * 16);
    }
    if (tid < 32) cp16(base + 2 * BREG + tid * 16, g_ext4 + (size_t)g * 32 + tid);
    asm volatile("cp.async.commit_group;" ::: "memory");
}

__global__ void __launch_bounds__(256, 3)
k_main_mma(int n) {
    __shared__ __align__(16) char smem[SMEMSZ];
    unsigned sb = (unsigned)__cvta_generic_to_shared(smem);
    const int tid = threadIdx.x, w = tid >> 5, lane = tid & 31;
    const int qblk = blockIdx.x, split = blockIdx.y;
    const int NT = (n / NTT) / TSPLIT;
    const int t0 = split * NT;

    // ---- stage A: hi rows (pitch 48) at sb, lo at sb+6144 ----
    {
        int row = tid >> 1, c = tid & 1;
        cp16(sb + row * PITCH + c * 16, g_A1 + (size_t)(qblk * MQ + row) * 32 + c * 16);
        cp16(sb + 6144 + row * PITCH + c * 16, g_A0 + (size_t)(qblk * MQ + row) * 32 + c * 16);
    }
    asm volatile("cp.async.commit_group;" ::: "memory");
    asm volatile("cp.async.wait_group 0;" ::: "memory");
    __syncthreads();

    unsigned a1[4], a0[4];
    {
        unsigned abase = sb + (w * 16 + (lane & 15)) * PITCH + (lane >> 4) * 16;
        ldmx4(a1, abase);
        ldmx4(a0, abase + 6144);
    }
    const int qg = lane >> 2;
    const unsigned long long cqa = dup2(g_qe[qblk * MQ + w * 16 + qg]);
    const unsigned long long cqb = dup2(g_qe[qblk * MQ + w * 16 + qg + 8]);
    unsigned long long KHH, KMX;
    {
        float cl = g_cl, K2 = cl + cl;
        float inv = K2 / (SCQ * SCQ);
        KHH = dup2(inv * 65536.0f);
        KMX = dup2(inv * 256.0f);
    }
    __syncthreads();                 // done with staged A

    load_tile(sb, t0, 0, tid);

    float num_a = 0.f, den_a = 0.f, num_b = 0.f, den_b = 0.f;
    const unsigned browAdd = (lane >> 4) * 8 + (lane & 7);
    const unsigned bcolb   = ((lane >> 3) & 1) * 16;

    for (int i = 0; i < NT; i++) {
        const int buf = i & 1;
        if (i + 1 < NT) {
            load_tile(sb, t0 + i + 1, buf ^ 1, tid);
            asm volatile("cp.async.wait_group 1;" ::: "memory");
        } else {
            asm volatile("cp.async.wait_group 0;" ::: "memory");
        }
        __syncthreads();

        const unsigned bbase = sb + buf * BUFSZ;
        const float4* ext = (const float4*)(smem + buf * BUFSZ + 2 * BREG);

        #pragma unroll
        for (int np = 0; np < 4; np++) {
            const unsigned rb = bbase + (np * 16 + browAdd) * PITCH + bcolb;
            unsigned b1v[4], b0v[4];
            ldmx4(b1v, rb);
            ldmx4(b0v, rb + BREG);
            #pragma unroll
            for (int ns = 0; ns < 2; ns++) {
                int chh[4] = {0, 0, 0, 0}, cmx[4] = {0, 0, 0, 0};
                mma_s8(chh, a1, b1v[ns * 2], b1v[ns * 2 + 1]);   // hi*hi  (scale 65536)
                mma_s8(cmx, a1, b0v[ns * 2], b0v[ns * 2 + 1]);   // hi*lo  (scale 256)
                mma_s8(cmx, a0, b1v[ns * 2], b1v[ns * 2 + 1]);   // lo*hi  (scale 256)
                // lo*lo dropped (≤1.3e-4 abs in dot)

                float4 e = ext[(np * 2 + ns) * 4 + (lane & 3)];
                unsigned long long ct = pack2(e.x, e.y);
                unsigned long long pa =
                    fma2(pack2((float)chh[0], (float)chh[1]), KHH,
                    fma2(pack2((float)cmx[0], (float)cmx[1]), KMX, add2(ct, cqa)));
                unsigned long long pb =
                    fma2(pack2((float)chh[2], (float)chh[3]), KHH,
                    fma2(pack2((float)cmx[2], (float)cmx[3]), KMX, add2(ct, cqb)));
                float2 fa = unpack2(pa), fb = unpack2(pb);
                float w0 = ex2f(fa.x), w1 = ex2f(fa.y);
                float w2 = ex2f(fb.x), w3 = ex2f(fb.y);
                num_a = fmaf(w0, e.z, num_a); num_a = fmaf(w1, e.w, num_a);
                den_a += w0 + w1;
                num_b = fmaf(w2, e.z, num_b); num_b = fmaf(w3, e.w, num_b);
                den_b += w2 + w3;
            }
        }
        __syncthreads();
    }

    #pragma unroll
    for (int o = 1; o <= 2; o <<= 1) {
        num_a += __shfl_xor_sync(~0u, num_a, o);
        den_a += __shfl_xor_sync(~0u, den_a, o);
        num_b += __shfl_xor_sync(~0u, num_b, o);
        den_b += __shfl_xor_sync(~0u, den_b, o);
    }
    if ((lane & 3) == 0) {
        int q = qblk * MQ + w * 16 + qg;
        g_pnd[q][split * 2]         = num_a;
        g_pnd[q][split * 2 + 1]     = den_a;
        g_pnd[q + 8][split * 2]     = num_b;
        g_pnd[q + 8][split * 2 + 1] = den_b;
    }
}

// ---------------- reduce + final ----------------
__global__ void k_reduce(const float* __restrict__ sig, int m) {
    __shared__ float s_rmin[8], s_rmax[8], s_smin[8], s_smax[8];
    int q = blockIdx.x * blockDim.x + threadIdx.x;
    float rx = 3.4e38f, rxmx = -3.4e38f, sg = 3.4e38f, sgmx = -3.4e38f;
    if (q < m) {
        const float4* p = (const float4*)g_pnd[q];
        float num = 0.f, den = 0.f;
        #pragma unroll
        for (int k = 0; k < 4; k++) {
            float4 v = p[k];
            num += v.x + v.z;
            den += v.y + v.w;
        }
        float r = num / (den + EPSV);
        g_rx[q] = r; rx = r; rxmx = r;
        float sv = sig[q]; sg = sv; sgmx = sv;
    }
    float wr0 = warp_min(rx), wr1 = warp_max(rxmx), ws0 = warp_min(sg), ws1 = warp_max(sgmx);
    int w = threadIdx.x >> 5, l = threadIdx.x & 31, nw = blockDim.x >> 5;
    if (l == 0) { s_rmin[w] = wr0; s_rmax[w] = wr1; s_smin[w] = ws0; s_smax[w] = ws1; }
    __syncthreads();
    if (threadIdx.x == 0) {
        float a = s_rmin[0], b = s_rmax[0], cc = s_smin[0], d = s_smax[0];
        for (int i = 1; i < nw; i++) {
            a = fminf(a, s_rmin[i]); b = fmaxf(b, s_rmax[i]);
            cc = fminf(cc, s_smin[i]); d = fmaxf(d, s_smax[i]);
        }
        atomicMin(&g_rmin, fenc(a)); atomicMax(&g_rmax, fenc(b));
        atomicMin(&g_smin, fenc(cc)); atomicMax(&g_smax, fenc(d));
    }
}
__global__ void k_final(const float* __restrict__ sig, float* __restrict__ out, int m) {
    int q = blockIdx.x * blockDim.x + threadIdx.x;
    if (q >= m) return;
    float t1 = 0.5f * (g_rx[q] - fdec(g_rmin)) / (fdec(g_rmax) - fdec(g_rmin) + EPSV);
    float t2 = 0.5f * (sig[q]  - fdec(g_smin)) / (fdec(g_smax) - fdec(g_smin) + EPSV);
    out[q] = t1 + t2;
}

// ---------------- launch ----------------
extern "C" void kernel_launch(void* const* d_in, const int* in_sizes, int n_in,
                              void* d_out, int out_size) {
    const float* x   = (const float*)d_in[0];
    const float* tx  = (const float*)d_in[1];
    const float* tr  = (const float*)d_in[2];
    const float* sig = (const float*)d_in[3];
    int m = in_sizes[0] / D;   // 16384
    int n = in_sizes[1] / D;   // 8192

    k_bw1<<<BWB, 256>>>(tx);
    k_bw2<<<1, 32>>>(n);
    k_qprep<<<m * 8 / 256, 256>>>(x, m);
    k_tprep<<<n * 8 / 256, 256>>>(tx, tr, n);
    dim3 grid(m / MQ, TSPLIT);
    k_main_mma<<<grid, 256>>>(n);
    k_reduce<<<(m + 255) / 256, 256>>>(sig, m);
    k_final<<<(m + 255) / 256, 256>>>(sig, (float*)d_out, m);
}

// round 11
// speedup vs baseline: 1.8794x; 1.8794x over previous
#include <cuda_runtime.h>
#include <cuda_bf16.h>
#include <math.h>

#define D        32
#define TSPLIT   8
#define NTT      128           // train per tile
#define MQ       128           // queries per CTA
#define M_MAX    16384
#define N_MAX    8192
#define EPSV     1e-8f
#define BWB      64

// smem pitch-80 rows. Buf: Bhi[0,10240) Blo[10240,20480) ext[20480,21504)
#define PITCH    80
#define OFFLO    10240
#define OFFEXT   20480
#define BUFSZ    21504
#define SMEMSZ   (2*BUFSZ)     // 43008; A staging (20480) aliases pre-loop

__device__ float         g_cl;
__device__ __nv_bfloat16 g_Ah[M_MAX * D];
__device__ __nv_bfloat16 g_Al[M_MAX * D];
__device__ __nv_bfloat16 g_Bh[N_MAX * D];
__device__ __nv_bfloat16 g_Bl[N_MAX * D];
__device__ float4        g_ext4[N_MAX / 2]; // {ct2_even, ct2_odd, r_even, r_odd}
__device__ float         g_qe[M_MAX];
__device__ double        g_bws [BWB * D];
__device__ double        g_bws2[BWB * D];
__device__ float         g_pnum[TSPLIT][M_MAX];
__device__ float         g_pden[TSPLIT][M_MAX];
__device__ float         g_rx[M_MAX];
__device__ unsigned int  g_rmin, g_rmax, g_smin, g_smax;

// ---------------- helpers ----------------
__device__ __forceinline__ unsigned long long pack2(float lo, float hi) {
    unsigned long long r; asm("mov.b64 %0, {%1, %2};" : "=l"(r) : "f"(lo), "f"(hi)); return r;
}
__device__ __forceinline__ unsigned long long dup2(float v) {
    unsigned long long r; asm("mov.b64 %0, {%1, %1};" : "=l"(r) : "f"(v)); return r;
}
__device__ __forceinline__ unsigned long long add2(unsigned long long a, unsigned long long b) {
    unsigned long long d; asm("add.rn.f32x2 %0, %1, %2;" : "=l"(d) : "l"(a), "l"(b)); return d;
}
__device__ __forceinline__ float2 unpack2(unsigned long long p) {
    float2 f; asm("mov.b64 {%0, %1}, %2;" : "=f"(f.x), "=f"(f.y) : "l"(p)); return f;
}
__device__ __forceinline__ float ex2f(float a) {
    float r; asm("ex2.approx.f32 %0, %1;" : "=f"(r) : "f"(a)); return r;
}
__device__ __forceinline__ void cp16(unsigned dst, const void* src) {
    asm volatile("cp.async.ca.shared.global [%0], [%1], 16;" :: "r"(dst), "l"(src));
}
__device__ __forceinline__ unsigned fenc(float f) {
    unsigned u = __float_as_uint(f); return (u & 0x80000000u) ? ~u : (u | 0x80000000u);
}
__device__ __forceinline__ float fdec(unsigned u) {
    u = (u & 0x80000000u) ? (u & 0x7fffffffu) : ~u; return __uint_as_float(u);
}
__device__ __forceinline__ float warp_min(float v) {
    #pragma unroll
    for (int o = 16; o; o >>= 1) v = fminf(v, __shfl_xor_sync(~0u, v, o));
    return v;
}
__device__ __forceinline__ float warp_max(float v) {
    #pragma unroll
    for (int o = 16; o; o >>= 1) v = fmaxf(v, __shfl_xor_sync(~0u, v, o));
    return v;
}
__device__ __forceinline__ void ldmx4(unsigned* r, unsigned addr) {
    asm volatile("ldmatrix.sync.aligned.m8n8.x4.shared.b16 {%0,%1,%2,%3}, [%4];"
                 : "=r"(r[0]), "=r"(r[1]), "=r"(r[2]), "=r"(r[3]) : "r"(addr));
}
__device__ __forceinline__ void mma16816(float* c, const unsigned* a, unsigned b0, unsigned b1) {
    asm volatile("mma.sync.aligned.m16n8k16.row.col.f32.bf16.bf16.f32 "
                 "{%0,%1,%2,%3}, {%4,%5,%6,%7}, {%8,%9}, {%0,%1,%2,%3};"
                 : "+f"(c[0]), "+f"(c[1]), "+f"(c[2]), "+f"(c[3])
                 : "r"(a[0]), "r"(a[1]), "r"(a[2]), "r"(a[3]), "r"(b0), "r"(b1));
}
__device__ __forceinline__ unsigned pbf2(float a, float b) {
    return (unsigned)__bfloat16_as_ushort(__float2bfloat16_rn(a)) |
           ((unsigned)__bfloat16_as_ushort(__float2bfloat16_rn(b)) << 16);
}

// ---------------- bandwidth ----------------
__global__ void k_bw1(const float* __restrict__ tx) {
    __shared__ double sds[8][8][4], sds2[8][8][4];
    const int tid = threadIdx.x, b = blockIdx.x;
    const float4* tx4 = (const float4*)tx;
    double s[4] = {0,0,0,0}, s2[4] = {0,0,0,0};
    #pragma unroll
    for (int it = 0; it < 4; it++) {
        float4 v = tx4[(size_t)(b * 128 + it * 32) * 8 + tid];
        double vx = v.x, vy = v.y, vz = v.z, vw = v.w;
        s[0] += vx; s2[0] += vx*vx; s[1] += vy; s2[1] += vy*vy;
        s[2] += vz; s2[2] += vz*vz; s[3] += vw; s2[3] += vw*vw;
    }
    #pragma unroll
    for (int o = 8; o <= 16; o <<= 1)
        #pragma unroll
        for (int k = 0; k < 4; k++) {
            s[k]  += __shfl_xor_sync(~0u, s[k],  o);
            s2[k] += __shfl_xor_sync(~0u, s2[k], o);
        }
    int w = tid >> 5, l = tid & 31;
    if (l < 8)
        #pragma unroll
        for (int k = 0; k < 4; k++) { sds[w][l][k] = s[k]; sds2[w][l][k] = s2[k]; }
    __syncthreads();
    if (tid < 8)
        #pragma unroll
        for (int k = 0; k < 4; k++) {
            double a = 0, a2 = 0;
            #pragma unroll
            for (int ww = 0; ww < 8; ww++) { a += sds[ww][tid][k]; a2 += sds2[ww][tid][k]; }
            g_bws[b * D + tid * 4 + k] = a; g_bws2[b * D + tid * 4 + k] = a2;
        }
}
__global__ void k_bw2(int n) {
    int d = threadIdx.x;
    double s = 0, s2 = 0;
    for (int b = 0; b < BWB; b++) { s += g_bws[b * D + d]; s2 += g_bws2[b * D + d]; }
    double mean = s / n, var = (s2 - n * mean * mean) / (n - 1);
    double sd = sqrt(var > 0.0 ? var : 0.0);
    #pragma unroll
    for (int o = 16; o; o >>= 1) sd += __shfl_xor_sync(~0u, sd, o);
    if (d == 0) {
        double bw = (sd / D) * exp(-log((double)n) / (D + 4));
        g_cl = (float)(1.0 / (2.0 * bw * bw) * 1.4426950408889634);
        g_rmin = ~0u; g_rmax = 0u; g_smin = ~0u; g_smax = 0u;
    }
}

// ---------------- coalesced prep: 8 threads per row ----------------
__global__ void k_qprep(const float* __restrict__ x, int m) {
    int idx = blockIdx.x * 256 + threadIdx.x;
    int row = idx >> 3, g = idx & 7;
    float4 v = ((const float4*)x)[(size_t)row * 8 + g];
    float s = fmaf(v.x, v.x, fmaf(v.y, v.y, fmaf(v.z, v.z, v.w * v.w)));
    s += __shfl_xor_sync(~0u, s, 1);
    s += __shfl_xor_sync(~0u, s, 2);
    s += __shfl_xor_sync(~0u, s, 4);
    float cl = g_cl, K2 = cl + cl;
    float sx = v.x * K2, sy = v.y * K2, sz = v.z * K2, sw = v.w * K2;
    __nv_bfloat16 hx = __float2bfloat16_rn(sx), hy = __float2bfloat16_rn(sy);
    __nv_bfloat16 hz = __float2bfloat16_rn(sz), hw = __float2bfloat16_rn(sw);
    uint2 hi, lo;
    hi.x = (unsigned)__bfloat16_as_ushort(hx) | ((unsigned)__bfloat16_as_ushort(hy) << 16);
    hi.y = (unsigned)__bfloat16_as_ushort(hz) | ((unsigned)__bfloat16_as_ushort(hw) << 16);
    lo.x = pbf2(sx - __bfloat162float(hx), sy - __bfloat162float(hy));
    lo.y = pbf2(sz - __bfloat162float(hz), sw - __bfloat162float(hw));
    ((uint2*)g_Ah)[(size_t)row * 8 + g] = hi;
    ((uint2*)g_Al)[(size_t)row * 8 + g] = lo;
    if (g == 0) g_qe[row] = -cl * s;
}
__global__ void k_tprep(const float* __restrict__ tx, const float* __restrict__ tr, int n) {
    int idx = blockIdx.x * 256 + threadIdx.x;
    int row = idx >> 3, g = idx & 7;
    float4 v = ((const float4*)tx)[(size_t)row * 8 + g];
    float s = fmaf(v.x, v.x, fmaf(v.y, v.y, fmaf(v.z, v.z, v.w * v.w)));
    s += __shfl_xor_sync(~0u, s, 1);
    s += __shfl_xor_sync(~0u, s, 2);
    s += __shfl_xor_sync(~0u, s, 4);
    __nv_bfloat16 hx = __float2bfloat16_rn(v.x), hy = __float2bfloat16_rn(v.y);
    __nv_bfloat16 hz = __float2bfloat16_rn(v.z), hw = __float2bfloat16_rn(v.w);
    uint2 hi, lo;
    hi.x = (unsigned)__bfloat16_as_ushort(hx) | ((unsigned)__bfloat16_as_ushort(hy) << 16);
    hi.y = (unsigned)__bfloat16_as_ushort(hz) | ((unsigned)__bfloat16_as_ushort(hw) << 16);
    lo.x = pbf2(v.x - __bfloat162float(hx), v.y - __bfloat162float(hy));
    lo.y = pbf2(v.z - __bfloat162float(hz), v.w - __bfloat162float(hw));
    ((uint2*)g_Bh)[(size_t)row * 8 + g] = hi;
    ((uint2*)g_Bl)[(size_t)row * 8 + g] = lo;
    if (g == 0) {
        float* e = (float*)&g_ext4[row >> 1];
        if (row & 1) { e[1] = -g_cl * s; e[3] = tr[row]; }
        else         { e[0] = -g_cl * s; e[2] = tr[row]; }
    }
}

// ---------------- HMMA KDE mainloop (NTT=128, interleaved epilogue) ----------------
__device__ __forceinline__ void load_tile(unsigned sb, int g, int b, int tid) {
    unsigned base = sb + b * BUFSZ;
    const __nv_bfloat16* sh = g_Bh + (size_t)g * NTT * D;
    const __nv_bfloat16* sl = g_Bl + (size_t)g * NTT * D;
    #pragma unroll
    for (int i = 0; i < 2; i++) {
        int idx = tid + i * 256, row = idx >> 2, c = idx & 3;
        cp16(base + row * PITCH + c * 16, sh + row * D + c * 8);
        cp16(base + OFFLO + row * PITCH + c * 16, sl + row * D + c * 8);
    }
    if (tid < 64) cp16(base + OFFEXT + tid * 16, g_ext4 + (size_t)g * 64 + tid);
    asm volatile("cp.async.commit_group;" ::: "memory");
}

__global__ void __launch_bounds__(256, 4)
k_main_mma(int n) {
    __shared__ __align__(16) char smem[SMEMSZ];
    unsigned sb = (unsigned)__cvta_generic_to_shared(smem);
    const int tid = threadIdx.x, w = tid >> 5, lane = tid & 31;
    const int qblk = blockIdx.x, split = blockIdx.y;
    const int NT = (n / NTT) / TSPLIT;       // 8 tiles
    const int t0 = split * NT;

    // ---- stage A (hi at sb, lo at sb+10240), extract frags, reuse smem ----
    #pragma unroll
    for (int i = 0; i < 2; i++) {
        int idx = tid + i * 256, row = idx >> 2, c = idx & 3;
        cp16(sb + row * PITCH + c * 16, g_Ah + (size_t)(qblk * MQ + row) * D + c * 8);
        cp16(sb + OFFLO + row * PITCH + c * 16, g_Al + (size_t)(qblk * MQ + row) * D + c * 8);
    }
    asm volatile("cp.async.commit_group;" ::: "memory");
    asm volatile("cp.async.wait_group 0;" ::: "memory");
    __syncthreads();

    unsigned ah[2][4], al[2][4];
    {
        unsigned rowsel = lane & 15, colb = (lane >> 4) * 16;
        unsigned abase = sb + (w * 16 + rowsel) * PITCH + colb;
        ldmx4(ah[0], abase);
        ldmx4(ah[1], abase + 32);
        ldmx4(al[0], abase + OFFLO);
        ldmx4(al[1], abase + OFFLO + 32);
    }
    const int qg = lane >> 2;
    const unsigned long long cq2a = dup2(g_qe[qblk * MQ + w * 16 + qg]);
    const unsigned long long cq2b = dup2(g_qe[qblk * MQ + w * 16 + qg + 8]);
    __syncthreads();

    load_tile(sb, t0, 0, tid);

    float num_a = 0.f, den_a = 0.f, num_b = 0.f, den_b = 0.f;

    const unsigned browAdd = (lane >> 4) * 8 + (lane & 7);
    const unsigned bcolb   = ((lane >> 3) & 1) * 16;

    for (int i = 0; i < NT; i++) {
        const int buf = i & 1;
        if (i + 1 < NT) {
            load_tile(sb, t0 + i + 1, buf ^ 1, tid);
            asm volatile("cp.async.wait_group 1;" ::: "memory");
        } else {
            asm volatile("cp.async.wait_group 0;" ::: "memory");
        }
        __syncthreads();

        const unsigned bbase = sb + buf * BUFSZ;
        const float4* ext = (const float4*)(smem + buf * BUFSZ + OFFEXT);

        #pragma unroll
        for (int np = 0; np < 8; np++) {
            const unsigned rb = bbase + (np * 16 + browAdd) * PITCH + bcolb;
            float c[2][4];
            #pragma unroll
            for (int s = 0; s < 2; s++)
                #pragma unroll
                for (int k = 0; k < 4; k++) c[s][k] = 0.f;

            #pragma unroll
            for (int ks = 0; ks < 2; ks++) {
                unsigned bh[4], bl[4];
                ldmx4(bh, rb + ks * 32);
                ldmx4(bl, rb + OFFLO + ks * 32);
                #pragma unroll
                for (int ns = 0; ns < 2; ns++) {
                    float* cc = c[ns];
                    mma16816(cc, ah[ks], bh[ns * 2], bh[ns * 2 + 1]);   // hh
                    mma16816(cc, al[ks], bh[ns * 2], bh[ns * 2 + 1]);   // lh
                    mma16816(cc, ah[ks], bl[ns * 2], bl[ns * 2 + 1]);   // hl
                }
            }

            #pragma unroll
            for (int ns = 0; ns < 2; ns++) {
                float4 e = ext[(np * 2 + ns) * 4 + (lane & 3)];
                unsigned long long ct = pack2(e.x, e.y);
                unsigned long long pa = add2(add2(pack2(c[ns][0], c[ns][1]), ct), cq2a);
                unsigned long long pb = add2(add2(pack2(c[ns][2], c[ns][3]), ct), cq2b);
                float2 fa = unpack2(pa), fb = unpack2(pb);
                float w0 = ex2f(fa.x), w1 = ex2f(fa.y);
                float w2 = ex2f(fb.x), w3 = ex2f(fb.y);
                num_a = fmaf(w0, e.z, num_a); num_a = fmaf(w1, e.w, num_a);
                den_a += w0 + w1;
                num_b = fmaf(w2, e.z, num_b); num_b = fmaf(w3, e.w, num_b);
                den_b += w2 + w3;
            }
        }
        __syncthreads();
    }

    #pragma unroll
    for (int o = 1; o <= 2; o <<= 1) {
        num_a += __shfl_xor_sync(~0u, num_a, o);
        den_a += __shfl_xor_sync(~0u, den_a, o);
        num_b += __shfl_xor_sync(~0u, num_b, o);
        den_b += __shfl_xor_sync(~0u, den_b, o);
    }
    if ((lane & 3) == 0) {
        int q = qblk * MQ + w * 16 + qg;
        g_pnum[split][q] = num_a;     g_pden[split][q] = den_a;
        g_pnum[split][q + 8] = num_b; g_pden[split][q + 8] = den_b;
    }
}

// ---------------- reduce + final ----------------
__global__ void k_reduce(const float* __restrict__ sig, int m) {
    __shared__ float s_rmin[8], s_rmax[8], s_smin[8], s_smax[8];
    int q = blockIdx.x * blockDim.x + threadIdx.x;
    float rx = 3.4e38f, rxmx = -3.4e38f, sg = 3.4e38f, sgmx = -3.4e38f;
    if (q < m) {
        float num = 0.f, den = 0.f;
        #pragma unroll
        for (int s = 0; s < TSPLIT; s++) { num += g_pnum[s][q]; den += g_pden[s][q]; }
        float r = num / (den + EPSV);
        g_rx[q] = r; rx = r; rxmx = r;
        float sv = sig[q]; sg = sv; sgmx = sv;
    }
    float wr0 = warp_min(rx), wr1 = warp_max(rxmx), ws0 = warp_min(sg), ws1 = warp_max(sgmx);
    int w = threadIdx.x >> 5, l = threadIdx.x & 31, nw = blockDim.x >> 5;
    if (l == 0) { s_rmin[w] = wr0; s_rmax[w] = wr1; s_smin[w] = ws0; s_smax[w] = ws1; }
    __syncthreads();
    if (threadIdx.x == 0) {
        float a = s_rmin[0], b = s_rmax[0], cc = s_smin[0], d = s_smax[0];
        for (int i = 1; i < nw; i++) {
            a = fminf(a, s_rmin[i]); b = fmaxf(b, s_rmax[i]);
            cc = fminf(cc, s_smin[i]); d = fmaxf(d, s_smax[i]);
        }
        atomicMin(&g_rmin, fenc(a)); atomicMax(&g_rmax, fenc(b));
        atomicMin(&g_smin, fenc(cc)); atomicMax(&g_smax, fenc(d));
    }
}
__global__ void k_final(const float* __restrict__ sig, float* __restrict__ out, int m) {
    int q = blockIdx.x * blockDim.x + threadIdx.x;
    if (q >= m) return;
    float t1 = 0.5f * (g_rx[q] - fdec(g_rmin)) / (fdec(g_rmax) - fdec(g_rmin) + EPSV);
    float t2 = 0.5f * (sig[q]  - fdec(g_smin)) / (fdec(g_smax) - fdec(g_smin) + EPSV);
    out[q] = t1 + t2;
}

// ---------------- launch ----------------
extern "C" void kernel_launch(void* const* d_in, const int* in_sizes, int n_in,
                              void* d_out, int out_size) {
    const float* x   = (const float*)d_in[0];
    const float* tx  = (const float*)d_in[1];
    const float* tr  = (const float*)d_in[2];
    const float* sig = (const float*)d_in[3];
    int m = in_sizes[0] / D;   // 16384
    int n = in_sizes[1] / D;   // 8192

    k_bw1<<<BWB, 256>>>(tx);
    k_bw2<<<1, 32>>>(n);
    k_qprep<<<m * 8 / 256, 256>>>(x, m);
    k_tprep<<<n * 8 / 256, 256>>>(tx, tr, n);
    dim3 grid(m / MQ, TSPLIT);
    k_main_mma<<<grid, 256>>>(n);
    k_reduce<<<(m + 255) / 256, 256>>>(sig, m);
    k_final<<<(m + 255) / 256, 256>>>(sig, (float*)d_out, m);
}

// round 12
// speedup vs baseline: 2.3027x; 1.2252x over previous
#include <cuda_runtime.h>
#include <cuda_fp16.h>
#include <math.h>

#define D        32
#define TSPLIT   8
#define NTT      128           // train per tile
#define MQ       128           // queries per CTA
#define M_MAX    16384
#define N_MAX    8192
#define EPSV     1e-8f
#define BWB      64

// smem pitch-80 rows. Buf: Bh[0,10240) ext[10240,11264)
#define PITCH    80
#define OFFEXT   10240
#define BUFSZ    11264
#define SMEMSZ   (2*BUFSZ)     // 22528; A staging (20480: hi@0, lo@10240) aliases pre-loop
#define OFFALO   10240

__device__ float        g_cl;
__device__ __half       g_Ah[M_MAX * D];    // K2-scaled query hi (fp16)
__device__ __half       g_Al[M_MAX * D];    // K2-scaled query lo (fp16)
__device__ __half       g_Bh[N_MAX * D];    // train quantized fp16
__device__ float4       g_ext4[N_MAX / 2];  // {ct2_even, ct2_odd, r_even, r_odd} (t2 from quantized)
__device__ float        g_qe[M_MAX];
__device__ double       g_bws [BWB * D];
__device__ double       g_bws2[BWB * D];
__device__ float        g_pnum[TSPLIT][M_MAX];
__device__ float        g_pden[TSPLIT][M_MAX];
__device__ float        g_rx[M_MAX];
__device__ unsigned int g_rmin, g_rmax, g_smin, g_smax;

// ---------------- helpers ----------------
__device__ __forceinline__ unsigned long long pack2(float lo, float hi) {
    unsigned long long r; asm("mov.b64 %0, {%1, %2};" : "=l"(r) : "f"(lo), "f"(hi)); return r;
}
__device__ __forceinline__ unsigned long long dup2(float v) {
    unsigned long long r; asm("mov.b64 %0, {%1, %1};" : "=l"(r) : "f"(v)); return r;
}
__device__ __forceinline__ unsigned long long add2(unsigned long long a, unsigned long long b) {
    unsigned long long d; asm("add.rn.f32x2 %0, %1, %2;" : "=l"(d) : "l"(a), "l"(b)); return d;
}
__device__ __forceinline__ float2 unpack2(unsigned long long p) {
    float2 f; asm("mov.b64 {%0, %1}, %2;" : "=f"(f.x), "=f"(f.y) : "l"(p)); return f;
}
__device__ __forceinline__ float ex2f(float a) {
    float r; asm("ex2.approx.f32 %0, %1;" : "=f"(r) : "f"(a)); return r;
}
__device__ __forceinline__ void cp16(unsigned dst, const void* src) {
    asm volatile("cp.async.ca.shared.global [%0], [%1], 16;" :: "r"(dst), "l"(src));
}
__device__ __forceinline__ unsigned fenc(float f) {
    unsigned u = __float_as_uint(f); return (u & 0x80000000u) ? ~u : (u | 0x80000000u);
}
__device__ __forceinline__ float fdec(unsigned u) {
    u = (u & 0x80000000u) ? (u & 0x7fffffffu) : ~u; return __uint_as_float(u);
}
__device__ __forceinline__ float warp_min(float v) {
    #pragma unroll
    for (int o = 16; o; o >>= 1) v = fminf(v, __shfl_xor_sync(~0u, v, o));
    return v;
}
__device__ __forceinline__ float warp_max(float v) {
    #pragma unroll
    for (int o = 16; o; o >>= 1) v = fmaxf(v, __shfl_xor_sync(~0u, v, o));
    return v;
}
__device__ __forceinline__ void ldmx4(unsigned* r, unsigned addr) {
    asm volatile("ldmatrix.sync.aligned.m8n8.x4.shared.b16 {%0,%1,%2,%3}, [%4];"
                 : "=r"(r[0]), "=r"(r[1]), "=r"(r[2]), "=r"(r[3]) : "r"(addr));
}
__device__ __forceinline__ void mma_f16(float* c, const unsigned* a, unsigned b0, unsigned b1) {
    asm volatile("mma.sync.aligned.m16n8k16.row.col.f32.f16.f16.f32 "
                 "{%0,%1,%2,%3}, {%4,%5,%6,%7}, {%8,%9}, {%0,%1,%2,%3};"
                 : "+f"(c[0]), "+f"(c[1]), "+f"(c[2]), "+f"(c[3])
                 : "r"(a[0]), "r"(a[1]), "r"(a[2]), "r"(a[3]), "r"(b0), "r"(b1));
}
__device__ __forceinline__ unsigned ph2(float a, float b) {
    return (unsigned)__half_as_ushort(__float2half_rn(a)) |
           ((unsigned)__half_as_ushort(__float2half_rn(b)) << 16);
}

// ---------------- bandwidth ----------------
__global__ void k_bw1(const float* __restrict__ tx) {
    __shared__ double sds[8][8][4], sds2[8][8][4];
    const int tid = threadIdx.x, b = blockIdx.x;
    const float4* tx4 = (const float4*)tx;
    double s[4] = {0,0,0,0}, s2[4] = {0,0,0,0};
    #pragma unroll
    for (int it = 0; it < 4; it++) {
        float4 v = tx4[(size_t)(b * 128 + it * 32) * 8 + tid];
        double vx = v.x, vy = v.y, vz = v.z, vw = v.w;
        s[0] += vx; s2[0] += vx*vx; s[1] += vy; s2[1] += vy*vy;
        s[2] += vz; s2[2] += vz*vz; s[3] += vw; s2[3] += vw*vw;
    }
    #pragma unroll
    for (int o = 8; o <= 16; o <<= 1)
        #pragma unroll
        for (int k = 0; k < 4; k++) {
            s[k]  += __shfl_xor_sync(~0u, s[k],  o);
            s2[k] += __shfl_xor_sync(~0u, s2[k], o);
        }
    int w = tid >> 5, l = tid & 31;
    if (l < 8)
        #pragma unroll
        for (int k = 0; k < 4; k++) { sds[w][l][k] = s[k]; sds2[w][l][k] = s2[k]; }
    __syncthreads();
    if (tid < 8)
        #pragma unroll
        for (int k = 0; k < 4; k++) {
            double a = 0, a2 = 0;
            #pragma unroll
            for (int ww = 0; ww < 8; ww++) { a += sds[ww][tid][k]; a2 += sds2[ww][tid][k]; }
            g_bws[b * D + tid * 4 + k] = a; g_bws2[b * D + tid * 4 + k] = a2;
        }
}
__global__ void k_bw2(int n) {
    int d = threadIdx.x;
    double s = 0, s2 = 0;
    for (int b = 0; b < BWB; b++) { s += g_bws[b * D + d]; s2 += g_bws2[b * D + d]; }
    double mean = s / n, var = (s2 - n * mean * mean) / (n - 1);
    double sd = sqrt(var > 0.0 ? var : 0.0);
    #pragma unroll
    for (int o = 16; o; o >>= 1) sd += __shfl_xor_sync(~0u, sd, o);
    if (d == 0) {
        double bw = (sd / D) * exp(-log((double)n) / (D + 4));
        g_cl = (float)(1.0 / (2.0 * bw * bw) * 1.4426950408889634);
        g_rmin = ~0u; g_rmax = 0u; g_smin = ~0u; g_smax = 0u;
    }
}

// ---------------- coalesced prep: 8 threads per row ----------------
__global__ void k_qprep(const float* __restrict__ x, int m) {
    int idx = blockIdx.x * 256 + threadIdx.x;
    int row = idx >> 3, g = idx & 7;
    float4 v = ((const float4*)x)[(size_t)row * 8 + g];
    float s = fmaf(v.x, v.x, fmaf(v.y, v.y, fmaf(v.z, v.z, v.w * v.w)));
    s += __shfl_xor_sync(~0u, s, 1);
    s += __shfl_xor_sync(~0u, s, 2);
    s += __shfl_xor_sync(~0u, s, 4);
    float cl = g_cl, K2 = cl + cl;
    float sx = v.x * K2, sy = v.y * K2, sz = v.z * K2, sw = v.w * K2;
    __half hx = __float2half_rn(sx), hy = __float2half_rn(sy);
    __half hz = __float2half_rn(sz), hw = __float2half_rn(sw);
    uint2 hi, lo;
    hi.x = (unsigned)__half_as_ushort(hx) | ((unsigned)__half_as_ushort(hy) << 16);
    hi.y = (unsigned)__half_as_ushort(hz) | ((unsigned)__half_as_ushort(hw) << 16);
    lo.x = ph2(sx - __half2float(hx), sy - __half2float(hy));
    lo.y = ph2(sz - __half2float(hz), sw - __half2float(hw));
    ((uint2*)g_Ah)[(size_t)row * 8 + g] = hi;
    ((uint2*)g_Al)[(size_t)row * 8 + g] = lo;
    if (g == 0) g_qe[row] = -cl * s;
}
__global__ void k_tprep(const float* __restrict__ tx, const float* __restrict__ tr, int n) {
    int idx = blockIdx.x * 256 + threadIdx.x;
    int row = idx >> 3, g = idx & 7;
    float4 v = ((const float4*)tx)[(size_t)row * 8 + g];
    // quantize FIRST; t2 computed from quantized values (consistent reinterpretation)
    __half hx = __float2half_rn(v.x), hy = __float2half_rn(v.y);
    __half hz = __float2half_rn(v.z), hw = __float2half_rn(v.w);
    float qx = __half2float(hx), qy = __half2float(hy);
    float qz = __half2float(hz), qw = __half2float(hw);
    float s = fmaf(qx, qx, fmaf(qy, qy, fmaf(qz, qz, qw * qw)));
    s += __shfl_xor_sync(~0u, s, 1);
    s += __shfl_xor_sync(~0u, s, 2);
    s += __shfl_xor_sync(~0u, s, 4);
    uint2 hi;
    hi.x = (unsigned)__half_as_ushort(hx) | ((unsigned)__half_as_ushort(hy) << 16);
    hi.y = (unsigned)__half_as_ushort(hz) | ((unsigned)__half_as_ushort(hw) << 16);
    ((uint2*)g_Bh)[(size_t)row * 8 + g] = hi;
    if (g == 0) {
        float* e = (float*)&g_ext4[row >> 1];
        if (row & 1) { e[1] = -g_cl * s; e[3] = tr[row]; }
        else         { e[0] = -g_cl * s; e[2] = tr[row]; }
    }
}

// ---------------- HMMA KDE mainloop (fp16 asymmetric, 4 MMAs/piece) ----------------
__device__ __forceinline__ void load_tile(unsigned sb, int g, int b, int tid) {
    unsigned base = sb + b * BUFSZ;
    const __half* sh = g_Bh + (size_t)g * NTT * D;
    #pragma unroll
    for (int i = 0; i < 2; i++) {
        int idx = tid + i * 256, row = idx >> 2, c = idx & 3;
        cp16(base + row * PITCH + c * 16, sh + row * D + c * 8);
    }
    if (tid < 64) cp16(base + OFFEXT + tid * 16, g_ext4 + (size_t)g * 64 + tid);
    asm volatile("cp.async.commit_group;" ::: "memory");
}

__global__ void __launch_bounds__(256, 4)
k_main_mma(int n) {
    __shared__ __align__(16) char smem[SMEMSZ];
    unsigned sb = (unsigned)__cvta_generic_to_shared(smem);
    const int tid = threadIdx.x, w = tid >> 5, lane = tid & 31;
    const int qblk = blockIdx.x, split = blockIdx.y;
    const int NT = (n / NTT) / TSPLIT;       // 8 tiles
    const int t0 = split * NT;

    // ---- stage A (hi at sb, lo at sb+OFFALO), extract frags, reuse smem ----
    #pragma unroll
    for (int i = 0; i < 2; i++) {
        int idx = tid + i * 256, row = idx >> 2, c = idx & 3;
        cp16(sb + row * PITCH + c * 16, g_Ah + (size_t)(qblk * MQ + row) * D + c * 8);
        cp16(sb + OFFALO + row * PITCH + c * 16, g_Al + (size_t)(qblk * MQ + row) * D + c * 8);
    }
    asm volatile("cp.async.commit_group;" ::: "memory");
    asm volatile("cp.async.wait_group 0;" ::: "memory");
    __syncthreads();

    unsigned ah[2][4], al[2][4];
    {
        unsigned rowsel = lane & 15, colb = (lane >> 4) * 16;
        unsigned abase = sb + (w * 16 + rowsel) * PITCH + colb;
        ldmx4(ah[0], abase);
        ldmx4(ah[1], abase + 32);
        ldmx4(al[0], abase + OFFALO);
        ldmx4(al[1], abase + OFFALO + 32);
    }
    const int qg = lane >> 2;
    const unsigned long long cq2a = dup2(g_qe[qblk * MQ + w * 16 + qg]);
    const unsigned long long cq2b = dup2(g_qe[qblk * MQ + w * 16 + qg + 8]);
    __syncthreads();

    load_tile(sb, t0, 0, tid);

    float num_a = 0.f, den_a = 0.f, num_b = 0.f, den_b = 0.f;

    const unsigned browAdd = (lane >> 4) * 8 + (lane & 7);
    const unsigned bcolb   = ((lane >> 3) & 1) * 16;

    for (int i = 0; i < NT; i++) {
        const int buf = i & 1;
        if (i + 1 < NT) {
            load_tile(sb, t0 + i + 1, buf ^ 1, tid);
            asm volatile("cp.async.wait_group 1;" ::: "memory");
        } else {
            asm volatile("cp.async.wait_group 0;" ::: "memory");
        }
        __syncthreads();

        const unsigned bbase = sb + buf * BUFSZ;
        const float4* ext = (const float4*)(smem + buf * BUFSZ + OFFEXT);

        #pragma unroll
        for (int np = 0; np < 8; np++) {
            const unsigned rb = bbase + (np * 16 + browAdd) * PITCH + bcolb;
            float c[2][4];
            #pragma unroll
            for (int s = 0; s < 2; s++)
                #pragma unroll
                for (int k = 0; k < 4; k++) c[s][k] = 0.f;

            #pragma unroll
            for (int ks = 0; ks < 2; ks++) {
                unsigned bv[4];
                ldmx4(bv, rb + ks * 32);
                #pragma unroll
                for (int ns = 0; ns < 2; ns++) {
                    float* cc = c[ns];
                    mma_f16(cc, ah[ks], bv[ns * 2], bv[ns * 2 + 1]);   // hi·b
                    mma_f16(cc, al[ks], bv[ns * 2], bv[ns * 2 + 1]);   // lo·b
                }
            }

            #pragma unroll
            for (int ns = 0; ns < 2; ns++) {
                float4 e = ext[(np * 2 + ns) * 4 + (lane & 3)];
                unsigned long long ct = pack2(e.x, e.y);
                unsigned long long pa = add2(add2(pack2(c[ns][0], c[ns][1]), ct), cq2a);
                unsigned long long pb = add2(add2(pack2(c[ns][2], c[ns][3]), ct), cq2b);
                float2 fa = unpack2(pa), fb = unpack2(pb);
                float w0 = ex2f(fa.x), w1 = ex2f(fa.y);
                float w2 = ex2f(fb.x), w3 = ex2f(fb.y);
                num_a = fmaf(w0, e.z, num_a); num_a = fmaf(w1, e.w, num_a);
                den_a += w0 + w1;
                num_b = fmaf(w2, e.z, num_b); num_b = fmaf(w3, e.w, num_b);
                den_b += w2 + w3;
            }
        }
        __syncthreads();
    }

    #pragma unroll
    for (int o = 1; o <= 2; o <<= 1) {
        num_a += __shfl_xor_sync(~0u, num_a, o);
        den_a += __shfl_xor_sync(~0u, den_a, o);
        num_b += __shfl_xor_sync(~0u, num_b, o);
        den_b += __shfl_xor_sync(~0u, den_b, o);
    }
    if ((lane & 3) == 0) {
        int q = qblk * MQ + w * 16 + qg;
        g_pnum[split][q] = num_a;     g_pden[split][q] = den_a;
        g_pnum[split][q + 8] = num_b; g_pden[split][q + 8] = den_b;
    }
}

// ---------------- reduce + final ----------------
__global__ void k_reduce(const float* __restrict__ sig, int m) {
    __shared__ float s_rmin[8], s_rmax[8], s_smin[8], s_smax[8];
    int q = blockIdx.x * blockDim.x + threadIdx.x;
    float rx = 3.4e38f, rxmx = -3.4e38f, sg = 3.4e38f, sgmx = -3.4e38f;
    if (q < m) {
        float num = 0.f, den = 0.f;
        #pragma unroll
        for (int s = 0; s < TSPLIT; s++) { num += g_pnum[s][q]; den += g_pden[s][q]; }
        float r = num / (den + EPSV);
        g_rx[q] = r; rx = r; rxmx = r;
        float sv = sig[q]; sg = sv; sgmx = sv;
    }
    float wr0 = warp_min(rx), wr1 = warp_max(rxmx), ws0 = warp_min(sg), ws1 = warp_max(sgmx);
    int w = threadIdx.x >> 5, l = threadIdx.x & 31, nw = blockDim.x >> 5;
    if (l == 0) { s_rmin[w] = wr0; s_rmax[w] = wr1; s_smin[w] = ws0; s_smax[w] = ws1; }
    __syncthreads();
    if (threadIdx.x == 0) {
        float a = s_rmin[0], b = s_rmax[0], cc = s_smin[0], d = s_smax[0];
        for (int i = 1; i < nw; i++) {
            a = fminf(a, s_rmin[i]); b = fmaxf(b, s_rmax[i]);
            cc = fminf(cc, s_smin[i]); d = fmaxf(d, s_smax[i]);
        }
        atomicMin(&g_rmin, fenc(a)); atomicMax(&g_rmax, fenc(b));
        atomicMin(&g_smin, fenc(cc)); atomicMax(&g_smax, fenc(d));
    }
}
__global__ void k_final(const float* __restrict__ sig, float* __restrict__ out, int m) {
    int q = blockIdx.x * blockDim.x + threadIdx.x;
    if (q >= m) return;
    float t1 = 0.5f * (g_rx[q] - fdec(g_rmin)) / (fdec(g_rmax) - fdec(g_rmin) + EPSV);
    float t2 = 0.5f * (sig[q]  - fdec(g_smin)) / (fdec(g_smax) - fdec(g_smin) + EPSV);
    out[q] = t1 + t2;
}

// ---------------- launch ----------------
extern "C" void kernel_launch(void* const* d_in, const int* in_sizes, int n_in,
                              void* d_out, int out_size) {
    const float* x   = (const float*)d_in[0];
    const float* tx  = (const float*)d_in[1];
    const float* tr  = (const float*)d_in[2];
    const float* sig = (const float*)d_in[3];
    int m = in_sizes[0] / D;   // 16384
    int n = in_sizes[1] / D;   // 8192

    k_bw1<<<BWB, 256>>>(tx);
    k_bw2<<<1, 32>>>(n);
    k_qprep<<<m * 8 / 256, 256>>>(x, m);
    k_tprep<<<n * 8 / 256, 256>>>(tx, tr, n);
    dim3 grid(m / MQ, TSPLIT);
    k_main_mma<<<grid, 256>>>(n);
    k_reduce<<<(m + 255) / 256, 256>>>(sig, m);
    k_final<<<(m + 255) / 256, 256>>>(sig, (float*)d_out, m);
}

// round 13
// speedup vs baseline: 2.5245x; 1.0963x over previous
#include <cuda_runtime.h>
#include <cuda_fp16.h>
#include <math.h>

#define D        32
#define TSPLIT   9
#define NTT      128           // train per tile
#define MQ       128           // queries per CTA
#define M_MAX    16384
#define N_MAX    8192
#define EPSV     1e-8f
#define BWB      64

// smem pitch-80 rows. Buf: Bh[0,10240) ext[10240,11264)
#define PITCH    80
#define OFFEXT   10240
#define BUFSZ    11264
#define SMEMSZ   (2*BUFSZ)     // A staging (10240) aliases buffer 0 pre-loop

__device__ float        g_cl;
__device__ __half       g_Ah[M_MAX * D];    // fp16(x) raw
__device__ __half       g_Bh[N_MAX * D];    // fp16(t) raw
__device__ float4       g_ext4[N_MAX / 2];  // {t2q_even, t2q_odd, r_even, r_odd} (t2 from quantized)
__device__ float        g_qe[M_MAX];        // q2 from quantized
__device__ double       g_bws [BWB * D];
__device__ double       g_bws2[BWB * D];
__device__ float        g_pnum[TSPLIT][M_MAX];
__device__ float        g_pden[TSPLIT][M_MAX];
__device__ float        g_rx[M_MAX];
__device__ unsigned int g_rmin, g_rmax, g_smin, g_smax;

// ---------------- helpers ----------------
__device__ __forceinline__ unsigned long long pack2(float lo, float hi) {
    unsigned long long r; asm("mov.b64 %0, {%1, %2};" : "=l"(r) : "f"(lo), "f"(hi)); return r;
}
__device__ __forceinline__ unsigned long long dup2(float v) {
    unsigned long long r; asm("mov.b64 %0, {%1, %1};" : "=l"(r) : "f"(v)); return r;
}
__device__ __forceinline__ unsigned long long fma2(unsigned long long a, unsigned long long b, unsigned long long c) {
    unsigned long long d; asm("fma.rn.f32x2 %0, %1, %2, %3;" : "=l"(d) : "l"(a), "l"(b), "l"(c)); return d;
}
__device__ __forceinline__ float2 unpack2(unsigned long long p) {
    float2 f; asm("mov.b64 {%0, %1}, %2;" : "=f"(f.x), "=f"(f.y) : "l"(p)); return f;
}
__device__ __forceinline__ float ex2f(float a) {
    float r; asm("ex2.approx.f32 %0, %1;" : "=f"(r) : "f"(a)); return r;
}
__device__ __forceinline__ void cp16(unsigned dst, const void* src) {
    asm volatile("cp.async.ca.shared.global [%0], [%1], 16;" :: "r"(dst), "l"(src));
}
__device__ __forceinline__ unsigned fenc(float f) {
    unsigned u = __float_as_uint(f); return (u & 0x80000000u) ? ~u : (u | 0x80000000u);
}
__device__ __forceinline__ float fdec(unsigned u) {
    u = (u & 0x80000000u) ? (u & 0x7fffffffu) : ~u; return __uint_as_float(u);
}
__device__ __forceinline__ float warp_min(float v) {
    #pragma unroll
    for (int o = 16; o; o >>= 1) v = fminf(v, __shfl_xor_sync(~0u, v, o));
    return v;
}
__device__ __forceinline__ float warp_max(float v) {
    #pragma unroll
    for (int o = 16; o; o >>= 1) v = fmaxf(v, __shfl_xor_sync(~0u, v, o));
    return v;
}
__device__ __forceinline__ void ldmx4(unsigned* r, unsigned addr) {
    asm volatile("ldmatrix.sync.aligned.m8n8.x4.shared.b16 {%0,%1,%2,%3}, [%4];"
                 : "=r"(r[0]), "=r"(r[1]), "=r"(r[2]), "=r"(r[3]) : "r"(addr));
}
__device__ __forceinline__ void mma_f16(float* c, const unsigned* a, unsigned b0, unsigned b1) {
    asm volatile("mma.sync.aligned.m16n8k16.row.col.f32.f16.f16.f32 "
                 "{%0,%1,%2,%3}, {%4,%5,%6,%7}, {%8,%9}, {%0,%1,%2,%3};"
                 : "+f"(c[0]), "+f"(c[1]), "+f"(c[2]), "+f"(c[3])
                 : "r"(a[0]), "r"(a[1]), "r"(a[2]), "r"(a[3]), "r"(b0), "r"(b1));
}

// ---------------- bandwidth ----------------
__global__ void k_bw1(const float* __restrict__ tx) {
    __shared__ double sds[8][8][4], sds2[8][8][4];
    const int tid = threadIdx.x, b = blockIdx.x;
    const float4* tx4 = (const float4*)tx;
    double s[4] = {0,0,0,0}, s2[4] = {0,0,0,0};
    #pragma unroll
    for (int it = 0; it < 4; it++) {
        float4 v = tx4[(size_t)(b * 128 + it * 32) * 8 + tid];
        double vx = v.x, vy = v.y, vz = v.z, vw = v.w;
        s[0] += vx; s2[0] += vx*vx; s[1] += vy; s2[1] += vy*vy;
        s[2] += vz; s2[2] += vz*vz; s[3] += vw; s2[3] += vw*vw;
    }
    #pragma unroll
    for (int o = 8; o <= 16; o <<= 1)
        #pragma unroll
        for (int k = 0; k < 4; k++) {
            s[k]  += __shfl_xor_sync(~0u, s[k],  o);
            s2[k] += __shfl_xor_sync(~0u, s2[k], o);
        }
    int w = tid >> 5, l = tid & 31;
    if (l < 8)
        #pragma unroll
        for (int k = 0; k < 4; k++) { sds[w][l][k] = s[k]; sds2[w][l][k] = s2[k]; }
    __syncthreads();
    if (tid < 8)
        #pragma unroll
        for (int k = 0; k < 4; k++) {
            double a = 0, a2 = 0;
            #pragma unroll
            for (int ww = 0; ww < 8; ww++) { a += sds[ww][tid][k]; a2 += sds2[ww][tid][k]; }
            g_bws[b * D + tid * 4 + k] = a; g_bws2[b * D + tid * 4 + k] = a2;
        }
}
__global__ void k_bw2(int n) {
    int d = threadIdx.x;
    double s = 0, s2 = 0;
    for (int b = 0; b < BWB; b++) { s += g_bws[b * D + d]; s2 += g_bws2[b * D + d]; }
    double mean = s / n, var = (s2 - n * mean * mean) / (n - 1);
    double sd = sqrt(var > 0.0 ? var : 0.0);
    #pragma unroll
    for (int o = 16; o; o >>= 1) sd += __shfl_xor_sync(~0u, sd, o);
    if (d == 0) {
        double bw = (sd / D) * exp(-log((double)n) / (D + 4));
        g_cl = (float)(1.0 / (2.0 * bw * bw) * 1.4426950408889634);
        g_rmin = ~0u; g_rmax = 0u; g_smin = ~0u; g_smax = 0u;
    }
}

// ---------------- fused prep (cl-independent): quantize + consistent norms ----
__global__ void k_prep(const float* __restrict__ x, const float* __restrict__ tx,
                       const float* __restrict__ tr, int m, int n) {
    int idx = blockIdx.x * 256 + threadIdx.x;
    int row = idx >> 3, g = idx & 7;
    const bool isq = (row < m);
    int r2 = isq ? row : row - m;
    const float4* src = isq ? (const float4*)x : (const float4*)tx;
    float4 v = src[(size_t)r2 * 8 + g];
    __half hx = __float2half_rn(v.x), hy = __float2half_rn(v.y);
    __half hz = __float2half_rn(v.z), hw = __float2half_rn(v.w);
    float qx = __half2float(hx), qy = __half2float(hy);
    float qz = __half2float(hz), qw = __half2float(hw);
    float s = fmaf(qx, qx, fmaf(qy, qy, fmaf(qz, qz, qw * qw)));
    s += __shfl_xor_sync(~0u, s, 1);
    s += __shfl_xor_sync(~0u, s, 2);
    s += __shfl_xor_sync(~0u, s, 4);
    uint2 hi;
    hi.x = (unsigned)__half_as_ushort(hx) | ((unsigned)__half_as_ushort(hy) << 16);
    hi.y = (unsigned)__half_as_ushort(hz) | ((unsigned)__half_as_ushort(hw) << 16);
    if (isq) {
        ((uint2*)g_Ah)[(size_t)r2 * 8 + g] = hi;
        if (g == 0) g_qe[r2] = s;
    } else {
        ((uint2*)g_Bh)[(size_t)r2 * 8 + g] = hi;
        if (g == 0) {
            float* e = (float*)&g_ext4[r2 >> 1];
            if (r2 & 1) { e[1] = s; e[3] = tr[r2]; }
            else        { e[0] = s; e[2] = tr[r2]; }
        }
    }
}

// ---------------- HMMA KDE mainloop (fp16 both sides, 2 MMAs/piece) ----------------
__device__ __forceinline__ void load_tile(unsigned sb, int g, int b, int tid) {
    unsigned base = sb + b * BUFSZ;
    const __half* sh = g_Bh + (size_t)g * NTT * D;
    #pragma unroll
    for (int i = 0; i < 2; i++) {
        int idx = tid + i * 256, row = idx >> 2, c = idx & 3;
        cp16(base + row * PITCH + c * 16, sh + row * D + c * 8);
    }
    if (tid < 64) cp16(base + OFFEXT + tid * 16, g_ext4 + (size_t)g * 64 + tid);
    asm volatile("cp.async.commit_group;" ::: "memory");
}

__global__ void __launch_bounds__(256, 4)
k_main_mma(int n) {
    __shared__ __align__(16) char smem[SMEMSZ];
    unsigned sb = (unsigned)__cvta_generic_to_shared(smem);
    const int tid = threadIdx.x, w = tid >> 5, lane = tid & 31;
    const int qblk = blockIdx.x, split = blockIdx.y;
    const int NTtot = n / NTT;                        // 64
    const int tb_lo = (split * NTtot) / TSPLIT;
    const int tb_hi = ((split + 1) * NTtot) / TSPLIT;

    // ---- stage A hi rows (pitch 80) at sb, extract frags, reuse smem ----
    #pragma unroll
    for (int i = 0; i < 2; i++) {
        int idx = tid + i * 256, row = idx >> 2, c = idx & 3;
        cp16(sb + row * PITCH + c * 16, g_Ah + (size_t)(qblk * MQ + row) * D + c * 8);
    }
    asm volatile("cp.async.commit_group;" ::: "memory");
    asm volatile("cp.async.wait_group 0;" ::: "memory");
    __syncthreads();

    unsigned ah[2][4];
    {
        unsigned rowsel = lane & 15, colb = (lane >> 4) * 16;
        unsigned abase = sb + (w * 16 + rowsel) * PITCH + colb;
        ldmx4(ah[0], abase);
        ldmx4(ah[1], abase + 32);
    }
    const int qg = lane >> 2;
    const float cl = g_cl;
    const unsigned long long negcl2 = dup2(-cl);
    const unsigned long long K2d    = dup2(cl + cl);
    const unsigned long long cqa = dup2(-cl * g_qe[qblk * MQ + w * 16 + qg]);
    const unsigned long long cqb = dup2(-cl * g_qe[qblk * MQ + w * 16 + qg + 8]);
    __syncthreads();

    load_tile(sb, tb_lo, 0, tid);

    float num_a = 0.f, den_a = 0.f, num_b = 0.f, den_b = 0.f;

    const unsigned browAdd = (lane >> 4) * 8 + (lane & 7);
    const unsigned bcolb   = ((lane >> 3) & 1) * 16;

    for (int tb = tb_lo; tb < tb_hi; tb++) {
        const int buf = (tb - tb_lo) & 1;
        if (tb + 1 < tb_hi) {
            load_tile(sb, tb + 1, buf ^ 1, tid);
            asm volatile("cp.async.wait_group 1;" ::: "memory");
        } else {
            asm volatile("cp.async.wait_group 0;" ::: "memory");
        }
        __syncthreads();

        const unsigned bbase = sb + buf * BUFSZ;
        const float4* ext = (const float4*)(smem + buf * BUFSZ + OFFEXT);

        #pragma unroll
        for (int np = 0; np < 8; np++) {
            const unsigned rb = bbase + (np * 16 + browAdd) * PITCH + bcolb;
            float c[2][4];
            #pragma unroll
            for (int s = 0; s < 2; s++)
                #pragma unroll
                for (int k = 0; k < 4; k++) c[s][k] = 0.f;

            #pragma unroll
            for (int ks = 0; ks < 2; ks++) {
                unsigned bv[4];
                ldmx4(bv, rb + ks * 32);
                mma_f16(c[0], ah[ks], bv[0], bv[1]);
                mma_f16(c[1], ah[ks], bv[2], bv[3]);
            }

            #pragma unroll
            for (int ns = 0; ns < 2; ns++) {
                float4 e = ext[(np * 2 + ns) * 4 + (lane & 3)];
                unsigned long long t2p = pack2(e.x, e.y);
                unsigned long long ba = fma2(t2p, negcl2, cqa);   // -cl t2 - cl q2
                unsigned long long bb = fma2(t2p, negcl2, cqb);
                unsigned long long pa = fma2(pack2(c[ns][0], c[ns][1]), K2d, ba);
                unsigned long long pb = fma2(pack2(c[ns][2], c[ns][3]), K2d, bb);
                float2 fa = unpack2(pa), fb = unpack2(pb);
                float w0 = ex2f(fa.x), w1 = ex2f(fa.y);
                float w2 = ex2f(fb.x), w3 = ex2f(fb.y);
                num_a = fmaf(w0, e.z, num_a); num_a = fmaf(w1, e.w, num_a);
                den_a += w0 + w1;
                num_b = fmaf(w2, e.z, num_b); num_b = fmaf(w3, e.w, num_b);
                den_b += w2 + w3;
            }
        }
        __syncthreads();
    }

    #pragma unroll
    for (int o = 1; o <= 2; o <<= 1) {
        num_a += __shfl_xor_sync(~0u, num_a, o);
        den_a += __shfl_xor_sync(~0u, den_a, o);
        num_b += __shfl_xor_sync(~0u, num_b, o);
        den_b += __shfl_xor_sync(~0u, den_b, o);
    }
    if ((lane & 3) == 0) {
        int q = qblk * MQ + w * 16 + qg;
        g_pnum[split][q] = num_a;     g_pden[split][q] = den_a;
        g_pnum[split][q + 8] = num_b; g_pden[split][q + 8] = den_b;
    }
}

// ---------------- reduce + final ----------------
__global__ void k_reduce(const float* __restrict__ sig, int m) {
    __shared__ float s_rmin[8], s_rmax[8], s_smin[8], s_smax[8];
    int q = blockIdx.x * blockDim.x + threadIdx.x;
    float rx = 3.4e38f, rxmx = -3.4e38f, sg = 3.4e38f, sgmx = -3.4e38f;
    if (q < m) {
        float num = 0.f, den = 0.f;
        #pragma unroll
        for (int s = 0; s < TSPLIT; s++) { num += g_pnum[s][q]; den += g_pden[s][q]; }
        float r = num / (den + EPSV);
        g_rx[q] = r; rx = r; rxmx = r;
        float sv = sig[q]; sg = sv; sgmx = sv;
    }
    float wr0 = warp_min(rx), wr1 = warp_max(rxmx), ws0 = warp_min(sg), ws1 = warp_max(sgmx);
    int w = threadIdx.x >> 5, l = threadIdx.x & 31, nw = blockDim.x >> 5;
    if (l == 0) { s_rmin[w] = wr0; s_rmax[w] = wr1; s_smin[w] = ws0; s_smax[w] = ws1; }
    __syncthreads();
    if (threadIdx.x == 0) {
        float a = s_rmin[0], b = s_rmax[0], cc = s_smin[0], d = s_smax[0];
        for (int i = 1; i < nw; i++) {
            a = fminf(a, s_rmin[i]); b = fmaxf(b, s_rmax[i]);
            cc = fminf(cc, s_smin[i]); d = fmaxf(d, s_smax[i]);
        }
        atomicMin(&g_rmin, fenc(a)); atomicMax(&g_rmax, fenc(b));
        atomicMin(&g_smin, fenc(cc)); atomicMax(&g_smax, fenc(d));
    }
}
__global__ void k_final(const float* __restrict__ sig, float* __restrict__ out, int m) {
    int q = blockIdx.x * blockDim.x + threadIdx.x;
    if (q >= m) return;
    float t1 = 0.5f * (g_rx[q] - fdec(g_rmin)) / (fdec(g_rmax) - fdec(g_rmin) + EPSV);
    float t2 = 0.5f * (sig[q]  - fdec(g_smin)) / (fdec(g_smax) - fdec(g_smin) + EPSV);
    out[q] = t1 + t2;
}

// ---------------- launch ----------------
extern "C" void kernel_launch(void* const* d_in, const int* in_sizes, int n_in,
                              void* d_out, int out_size) {
    const float* x   = (const float*)d_in[0];
    const float* tx  = (const float*)d_in[1];
    const float* tr  = (const float*)d_in[2];
    const float* sig = (const float*)d_in[3];
    int m = in_sizes[0] / D;   // 16384
    int n = in_sizes[1] / D;   // 8192

    k_prep<<<(m + n) * 8 / 256, 256>>>(x, tx, tr, m, n);
    k_bw1<<<BWB, 256>>>(tx);
    k_bw2<<<1, 32>>>(n);
    dim3 grid(m / MQ, TSPLIT);
    k_main_mma<<<grid, 256>>>(n);
    k_reduce<<<(m + 255) / 256, 256>>>(sig, m);
    k_final<<<(m + 255) / 256, 256>>>(sig, (float*)d_out, m);
}

// round 14
// speedup vs baseline: 2.7116x; 1.0741x over previous
#include <cuda_runtime.h>
#include <cuda_fp16.h>
#include <math.h>

#define D        32
#define TSMAX    7
#define NTT      128           // train per tile
#define MQ       128           // queries per CTA
#define M_MAX    16384
#define N_MAX    8192
#define EPSV     1e-8f
#define BWB      64

// smem pitch-80 rows. Buf: Bh[0,10240) ext[10240,11264)
#define PITCH    80
#define OFFEXT   10240
#define BUFSZ    11264
#define SMEMSZ   (2*BUFSZ)     // A staging (10240) aliases buffer 0 pre-loop

__device__ float        g_cl;
__device__ __half       g_Ah[M_MAX * D];    // fp16(x)
__device__ __half       g_Bh[N_MAX * D];    // fp16(t)
__device__ float4       g_ext4[N_MAX / 2];  // {t2q_even, t2q_odd, r_even, r_odd}
__device__ float        g_qe[M_MAX];        // q2 from quantized
__device__ double       g_bws [BWB * D];
__device__ double       g_bws2[BWB * D];
__device__ float        g_pnum[TSMAX][M_MAX];
__device__ float        g_pden[TSMAX][M_MAX];
__device__ float        g_rx[M_MAX];
__device__ unsigned int g_rmin, g_rmax, g_smin, g_smax;

// ---------------- helpers ----------------
__device__ __forceinline__ unsigned long long pack2(float lo, float hi) {
    unsigned long long r; asm("mov.b64 %0, {%1, %2};" : "=l"(r) : "f"(lo), "f"(hi)); return r;
}
__device__ __forceinline__ unsigned long long dup2(float v) {
    unsigned long long r; asm("mov.b64 %0, {%1, %1};" : "=l"(r) : "f"(v)); return r;
}
__device__ __forceinline__ unsigned long long fma2(unsigned long long a, unsigned long long b, unsigned long long c) {
    unsigned long long d; asm("fma.rn.f32x2 %0, %1, %2, %3;" : "=l"(d) : "l"(a), "l"(b), "l"(c)); return d;
}
__device__ __forceinline__ float2 unpack2(unsigned long long p) {
    float2 f; asm("mov.b64 {%0, %1}, %2;" : "=f"(f.x), "=f"(f.y) : "l"(p)); return f;
}
__device__ __forceinline__ float ex2f(float a) {
    float r; asm("ex2.approx.f32 %0, %1;" : "=f"(r) : "f"(a)); return r;
}
__device__ __forceinline__ void cp16(unsigned dst, const void* src) {
    asm volatile("cp.async.ca.shared.global [%0], [%1], 16;" :: "r"(dst), "l"(src));
}
__device__ __forceinline__ unsigned fenc(float f) {
    unsigned u = __float_as_uint(f); return (u & 0x80000000u) ? ~u : (u | 0x80000000u);
}
__device__ __forceinline__ float fdec(unsigned u) {
    u = (u & 0x80000000u) ? (u & 0x7fffffffu) : ~u; return __uint_as_float(u);
}
__device__ __forceinline__ float warp_min(float v) {
    #pragma unroll
    for (int o = 16; o; o >>= 1) v = fminf(v, __shfl_xor_sync(~0u, v, o));
    return v;
}
__device__ __forceinline__ float warp_max(float v) {
    #pragma unroll
    for (int o = 16; o; o >>= 1) v = fmaxf(v, __shfl_xor_sync(~0u, v, o));
    return v;
}
__device__ __forceinline__ void ldmx4(unsigned* r, unsigned addr) {
    asm volatile("ldmatrix.sync.aligned.m8n8.x4.shared.b16 {%0,%1,%2,%3}, [%4];"
                 : "=r"(r[0]), "=r"(r[1]), "=r"(r[2]), "=r"(r[3]) : "r"(addr));
}
__device__ __forceinline__ void mma_f16(float* c, const unsigned* a, unsigned b0, unsigned b1) {
    asm volatile("mma.sync.aligned.m16n8k16.row.col.f32.f16.f16.f32 "
                 "{%0,%1,%2,%3}, {%4,%5,%6,%7}, {%8,%9}, {%0,%1,%2,%3};"
                 : "+f"(c[0]), "+f"(c[1]), "+f"(c[2]), "+f"(c[3])
                 : "r"(a[0]), "r"(a[1]), "r"(a[2]), "r"(a[3]), "r"(b0), "r"(b1));
}

// ---------------- fused prep + bandwidth phase 1 ----------------
// blocks 0..63: per-dim partial sums for Scott bandwidth (reads raw tx)
// blocks 64..831: fp16 quantize + consistent squared norms for x and tx
__global__ void k_prepbw(const float* __restrict__ x, const float* __restrict__ tx,
                         const float* __restrict__ tr, int m, int n) {
    __shared__ double sds[8][8][4], sds2[8][8][4];
    const int tid = threadIdx.x;
    if (blockIdx.x < BWB) {
        const int b = blockIdx.x;
        const float4* tx4 = (const float4*)tx;
        double s[4] = {0,0,0,0}, s2[4] = {0,0,0,0};
        #pragma unroll
        for (int it = 0; it < 4; it++) {
            float4 v = tx4[(size_t)(b * 128 + it * 32) * 8 + tid];
            double vx = v.x, vy = v.y, vz = v.z, vw = v.w;
            s[0] += vx; s2[0] += vx*vx; s[1] += vy; s2[1] += vy*vy;
            s[2] += vz; s2[2] += vz*vz; s[3] += vw; s2[3] += vw*vw;
        }
        #pragma unroll
        for (int o = 8; o <= 16; o <<= 1)
            #pragma unroll
            for (int k = 0; k < 4; k++) {
                s[k]  += __shfl_xor_sync(~0u, s[k],  o);
                s2[k] += __shfl_xor_sync(~0u, s2[k], o);
            }
        int w = tid >> 5, l = tid & 31;
        if (l < 8)
            #pragma unroll
            for (int k = 0; k < 4; k++) { sds[w][l][k] = s[k]; sds2[w][l][k] = s2[k]; }
        __syncthreads();
        if (tid < 8)
            #pragma unroll
            for (int k = 0; k < 4; k++) {
                double a = 0, a2 = 0;
                #pragma unroll
                for (int ww = 0; ww < 8; ww++) { a += sds[ww][tid][k]; a2 += sds2[ww][tid][k]; }
                g_bws[b * D + tid * 4 + k] = a; g_bws2[b * D + tid * 4 + k] = a2;
            }
        return;
    }
    int idx = (blockIdx.x - BWB) * 256 + tid;
    int row = idx >> 3, g = idx & 7;
    const bool isq = (row < m);
    int r2 = isq ? row : row - m;
    const float4* src = isq ? (const float4*)x : (const float4*)tx;
    float4 v = src[(size_t)r2 * 8 + g];
    __half hx = __float2half_rn(v.x), hy = __float2half_rn(v.y);
    __half hz = __float2half_rn(v.z), hw = __float2half_rn(v.w);
    float qx = __half2float(hx), qy = __half2float(hy);
    float qz = __half2float(hz), qw = __half2float(hw);
    float s = fmaf(qx, qx, fmaf(qy, qy, fmaf(qz, qz, qw * qw)));
    s += __shfl_xor_sync(~0u, s, 1);
    s += __shfl_xor_sync(~0u, s, 2);
    s += __shfl_xor_sync(~0u, s, 4);
    uint2 hi;
    hi.x = (unsigned)__half_as_ushort(hx) | ((unsigned)__half_as_ushort(hy) << 16);
    hi.y = (unsigned)__half_as_ushort(hz) | ((unsigned)__half_as_ushort(hw) << 16);
    if (isq) {
        ((uint2*)g_Ah)[(size_t)r2 * 8 + g] = hi;
        if (g == 0) {
            g_qe[r2] = s;
            if (r2 >= (M_MAX / MQ - 8) * MQ) {           // qblks 120..127 use 6 splits
                g_pnum[TSMAX - 1][r2] = 0.f;
                g_pden[TSMAX - 1][r2] = 0.f;
            }
        }
    } else {
        ((uint2*)g_Bh)[(size_t)r2 * 8 + g] = hi;
        if (g == 0) {
            float* e = (float*)&g_ext4[r2 >> 1];
            if (r2 & 1) { e[1] = s; e[3] = tr[r2]; }
            else        { e[0] = s; e[2] = tr[r2]; }
        }
    }
}

// ---------------- bandwidth phase 2 ----------------
__global__ void k_bw2(int n) {
    int d = threadIdx.x;
    double s = 0, s2 = 0;
    for (int b = 0; b < BWB; b++) { s += g_bws[b * D + d]; s2 += g_bws2[b * D + d]; }
    double mean = s / n, var = (s2 - n * mean * mean) / (n - 1);
    double sd = sqrt(var > 0.0 ? var : 0.0);
    #pragma unroll
    for (int o = 16; o; o >>= 1) sd += __shfl_xor_sync(~0u, sd, o);
    if (d == 0) {
        double bw = (sd / D) * exp(-log((double)n) / (D + 4));
        g_cl = (float)(1.0 / (2.0 * bw * bw) * 1.4426950408889634);
        g_rmin = ~0u; g_rmax = 0u; g_smin = ~0u; g_smax = 0u;
    }
}

// ---------------- HMMA KDE mainloop: 4 warps x 32 queries, occ 6 ----------------
__device__ __forceinline__ void load_tile(unsigned sb, int g, int b, int tid) {
    unsigned base = sb + b * BUFSZ;
    const __half* sh = g_Bh + (size_t)g * NTT * D;
    #pragma unroll
    for (int i = 0; i < 4; i++) {
        int idx = tid + i * 128, row = idx >> 2, c = idx & 3;
        cp16(base + row * PITCH + c * 16, sh + row * D + c * 8);
    }
    if (tid < 64) cp16(base + OFFEXT + tid * 16, g_ext4 + (size_t)g * 64 + tid);
    asm volatile("cp.async.commit_group;" ::: "memory");
}

__global__ void __launch_bounds__(128, 6)
k_main_mma(int n) {
    __shared__ __align__(16) char smem[SMEMSZ];
    unsigned sb = (unsigned)__cvta_generic_to_shared(smem);
    const int tid = threadIdx.x, w = tid >> 5, lane = tid & 31;
    const int qblk  = blockIdx.x & 127;
    const int split = blockIdx.x >> 7;
    const int S = (qblk < 120) ? 7 : 6;              // grid = 888 = 148*6 exactly
    const int NTtot = n / NTT;                       // 64
    const int tb_lo = (split * NTtot) / S;
    const int tb_hi = ((split + 1) * NTtot) / S;

    // ---- stage A (128 rows, pitch 80) at sb, extract frags, reuse smem ----
    #pragma unroll
    for (int i = 0; i < 4; i++) {
        int idx = tid + i * 128, row = idx >> 2, c = idx & 3;
        cp16(sb + row * PITCH + c * 16, g_Ah + (size_t)(qblk * MQ + row) * D + c * 8);
    }
    asm volatile("cp.async.commit_group;" ::: "memory");
    asm volatile("cp.async.wait_group 0;" ::: "memory");
    __syncthreads();

    unsigned ah0[2][4], ah1[2][4];                   // warp owns rows w*32..w*32+31
    {
        unsigned rowsel = lane & 15, colb = (lane >> 4) * 16;
        unsigned ab0 = sb + (w * 32 + rowsel) * PITCH + colb;
        unsigned ab1 = ab0 + 16 * PITCH;
        ldmx4(ah0[0], ab0);
        ldmx4(ah0[1], ab0 + 32);
        ldmx4(ah1[0], ab1);
        ldmx4(ah1[1], ab1 + 32);
    }
    const int qg = lane >> 2;
    const float cl = g_cl;
    const unsigned long long negcl2 = dup2(-cl);
    const unsigned long long K2d    = dup2(cl + cl);
    const int qbase = qblk * MQ + w * 32;
    const unsigned long long cqa0 = dup2(-cl * g_qe[qbase + qg]);
    const unsigned long long cqb0 = dup2(-cl * g_qe[qbase + qg + 8]);
    const unsigned long long cqa1 = dup2(-cl * g_qe[qbase + qg + 16]);
    const unsigned long long cqb1 = dup2(-cl * g_qe[qbase + qg + 24]);
    __syncthreads();

    load_tile(sb, tb_lo, 0, tid);

    float na0 = 0.f, da0 = 0.f, nb0 = 0.f, db0 = 0.f;
    float na1 = 0.f, da1 = 0.f, nb1 = 0.f, db1 = 0.f;

    const unsigned browAdd = (lane >> 4) * 8 + (lane & 7);
    const unsigned bcolb   = ((lane >> 3) & 1) * 16;

    for (int tb = tb_lo; tb < tb_hi; tb++) {
        const int buf = (tb - tb_lo) & 1;
        if (tb + 1 < tb_hi) {
            load_tile(sb, tb + 1, buf ^ 1, tid);
            asm volatile("cp.async.wait_group 1;" ::: "memory");
        } else {
            asm volatile("cp.async.wait_group 0;" ::: "memory");
        }
        __syncthreads();

        const unsigned bbase = sb + buf * BUFSZ;
        const float4* ext = (const float4*)(smem + buf * BUFSZ + OFFEXT);

        #pragma unroll
        for (int np = 0; np < 8; np++) {
            const unsigned rb = bbase + (np * 16 + browAdd) * PITCH + bcolb;
            float c0[2][4], c1[2][4];
            #pragma unroll
            for (int s = 0; s < 2; s++)
                #pragma unroll
                for (int k = 0; k < 4; k++) { c0[s][k] = 0.f; c1[s][k] = 0.f; }

            #pragma unroll
            for (int ks = 0; ks < 2; ks++) {
                unsigned bv[4];
                ldmx4(bv, rb + ks * 32);
                mma_f16(c0[0], ah0[ks], bv[0], bv[1]);
                mma_f16(c0[1], ah0[ks], bv[2], bv[3]);
                mma_f16(c1[0], ah1[ks], bv[0], bv[1]);
                mma_f16(c1[1], ah1[ks], bv[2], bv[3]);
            }

            #pragma unroll
            for (int ns = 0; ns < 2; ns++) {
                float4 e = ext[(np * 2 + ns) * 4 + (lane & 3)];
                unsigned long long t2p = pack2(e.x, e.y);
                unsigned long long ba0 = fma2(t2p, negcl2, cqa0);
                unsigned long long bb0 = fma2(t2p, negcl2, cqb0);
                unsigned long long ba1 = fma2(t2p, negcl2, cqa1);
                unsigned long long bb1 = fma2(t2p, negcl2, cqb1);
                unsigned long long pa0 = fma2(pack2(c0[ns][0], c0[ns][1]), K2d, ba0);
                unsigned long long pb0 = fma2(pack2(c0[ns][2], c0[ns][3]), K2d, bb0);
                unsigned long long pa1 = fma2(pack2(c1[ns][0], c1[ns][1]), K2d, ba1);
                unsigned long long pb1 = fma2(pack2(c1[ns][2], c1[ns][3]), K2d, bb1);
                float2 f0 = unpack2(pa0), f1 = unpack2(pb0);
                float2 f2 = unpack2(pa1), f3 = unpack2(pb1);
                float w0 = ex2f(f0.x), w1 = ex2f(f0.y);
                float w2 = ex2f(f1.x), w3 = ex2f(f1.y);
                float w4 = ex2f(f2.x), w5 = ex2f(f2.y);
                float w6 = ex2f(f3.x), w7 = ex2f(f3.y);
                na0 = fmaf(w0, e.z, na0); na0 = fmaf(w1, e.w, na0); da0 += w0 + w1;
                nb0 = fmaf(w2, e.z, nb0); nb0 = fmaf(w3, e.w, nb0); db0 += w2 + w3;
                na1 = fmaf(w4, e.z, na1); na1 = fmaf(w5, e.w, na1); da1 += w4 + w5;
                nb1 = fmaf(w6, e.z, nb1); nb1 = fmaf(w7, e.w, nb1); db1 += w6 + w7;
            }
        }
        __syncthreads();
    }

    #pragma unroll
    for (int o = 1; o <= 2; o <<= 1) {
        na0 += __shfl_xor_sync(~0u, na0, o); da0 += __shfl_xor_sync(~0u, da0, o);
        nb0 += __shfl_xor_sync(~0u, nb0, o); db0 += __shfl_xor_sync(~0u, db0, o);
        na1 += __shfl_xor_sync(~0u, na1, o); da1 += __shfl_xor_sync(~0u, da1, o);
        nb1 += __shfl_xor_sync(~0u, nb1, o); db1 += __shfl_xor_sync(~0u, db1, o);
    }
    if ((lane & 3) == 0) {
        int q = qbase + qg;
        g_pnum[split][q]      = na0; g_pden[split][q]      = da0;
        g_pnum[split][q + 8]  = nb0; g_pden[split][q + 8]  = db0;
        g_pnum[split][q + 16] = na1; g_pden[split][q + 16] = da1;
        g_pnum[split][q + 24] = nb1; g_pden[split][q + 24] = db1;
    }
}

// ---------------- reduce + final ----------------
__global__ void k_reduce(const float* __restrict__ sig, int m) {
    __shared__ float s_rmin[8], s_rmax[8], s_smin[8], s_smax[8];
    int q = blockIdx.x * blockDim.x + threadIdx.x;
    float rx = 3.4e38f, rxmx = -3.4e38f, sg = 3.4e38f, sgmx = -3.4e38f;
    if (q < m) {
        float num = 0.f, den = 0.f;
        #pragma unroll
        for (int s = 0; s < TSMAX; s++) { num += g_pnum[s][q]; den += g_pden[s][q]; }
        float r = num / (den + EPSV);
        g_rx[q] = r; rx = r; rxmx = r;
        float sv = sig[q]; sg = sv; sgmx = sv;
    }
    float wr0 = warp_min(rx), wr1 = warp_max(rxmx), ws0 = warp_min(sg), ws1 = warp_max(sgmx);
    int w = threadIdx.x >> 5, l = threadIdx.x & 31, nw = blockDim.x >> 5;
    if (l == 0) { s_rmin[w] = wr0; s_rmax[w] = wr1; s_smin[w] = ws0; s_smax[w] = ws1; }
    __syncthreads();
    if (threadIdx.x == 0) {
        float a = s_rmin[0], b = s_rmax[0], cc = s_smin[0], d = s_smax[0];
        for (int i = 1; i < nw; i++) {
            a = fminf(a, s_rmin[i]); b = fmaxf(b, s_rmax[i]);
            cc = fminf(cc, s_smin[i]); d = fmaxf(d, s_smax[i]);
        }
        atomicMin(&g_rmin, fenc(a)); atomicMax(&g_rmax, fenc(b));
        atomicMin(&g_smin, fenc(cc)); atomicMax(&g_smax, fenc(d));
    }
}
__global__ void k_final(const float* __restrict__ sig, float* __restrict__ out, int m) {
    int q = blockIdx.x * blockDim.x + threadIdx.x;
    if (q >= m) return;
    float t1 = 0.5f * (g_rx[q] - fdec(g_rmin)) / (fdec(g_rmax) - fdec(g_rmin) + EPSV);
    float t2 = 0.5f * (sig[q]  - fdec(g_smin)) / (fdec(g_smax) - fdec(g_smin) + EPSV);
    out[q] = t1 + t2;
}

// ---------------- launch ----------------
extern "C" void kernel_launch(void* const* d_in, const int* in_sizes, int n_in,
                              void* d_out, int out_size) {
    const float* x   = (const float*)d_in[0];
    const float* tx  = (const float*)d_in[1];
    const float* tr  = (const float*)d_in[2];
    const float* sig = (const float*)d_in[3];
    int m = in_sizes[0] / D;   // 16384
    int n = in_sizes[1] / D;   // 8192

    k_prepbw<<<BWB + (m + n) * 8 / 256, 256>>>(x, tx, tr, m, n);
    k_bw2<<<1, 32>>>(n);
    k_main_mma<<<888, 128>>>(n);
    k_reduce<<<(m + 255) / 256, 256>>>(sig, m);
    k_final<<<(m + 255) / 256, 256>>>(sig, (float*)d_out, m);
}

// round 15
// speedup vs baseline: 2.7924x; 1.0298x over previous
#include <cuda_runtime.h>
#include <cuda_fp16.h>
#include <math.h>

#define D        32
#define TSMAX    9
#define NTT      128           // train per tile
#define MQ       128           // queries per CTA
#define M_MAX    16384
#define N_MAX    8192
#define EPSV     1e-8f
#define BWB      64

// smem pitch-80 rows. Buf: Bh[0,10240) ext[10240,11264)
#define PITCH    80
#define OFFEXT   10240
#define BUFSZ    11264
#define SMEMSZ   (2*BUFSZ)     // A staging (10240) aliases buffer 0 pre-loop

__device__ float        g_cl;
__device__ __half       g_Ah[M_MAX * D];    // fp16(x)
__device__ __half       g_Bh[N_MAX * D];    // fp16(t)
__device__ float4       g_ext4[N_MAX / 2];  // {t2q_even, t2q_odd, r_even, r_odd}
__device__ float        g_qe[M_MAX];        // q2 from quantized
__device__ double       g_bws [BWB * D];
__device__ double       g_bws2[BWB * D];
__device__ float        g_pnum[TSMAX][M_MAX];
__device__ float        g_pden[TSMAX][M_MAX];
__device__ unsigned int g_rmin, g_rmax, g_smin, g_smax;
__device__ unsigned int g_cnt;

// ---------------- helpers ----------------
__device__ __forceinline__ unsigned long long pack2(float lo, float hi) {
    unsigned long long r; asm("mov.b64 %0, {%1, %2};" : "=l"(r) : "f"(lo), "f"(hi)); return r;
}
__device__ __forceinline__ unsigned long long dup2(float v) {
    unsigned long long r; asm("mov.b64 %0, {%1, %1};" : "=l"(r) : "f"(v)); return r;
}
__device__ __forceinline__ unsigned long long fma2(unsigned long long a, unsigned long long b, unsigned long long c) {
    unsigned long long d; asm("fma.rn.f32x2 %0, %1, %2, %3;" : "=l"(d) : "l"(a), "l"(b), "l"(c)); return d;
}
__device__ __forceinline__ float2 unpack2(unsigned long long p) {
    float2 f; asm("mov.b64 {%0, %1}, %2;" : "=f"(f.x), "=f"(f.y) : "l"(p)); return f;
}
__device__ __forceinline__ float ex2f(float a) {
    float r; asm("ex2.approx.f32 %0, %1;" : "=f"(r) : "f"(a)); return r;
}
__device__ __forceinline__ void cp16(unsigned dst, const void* src) {
    asm volatile("cp.async.ca.shared.global [%0], [%1], 16;" :: "r"(dst), "l"(src));
}
__device__ __forceinline__ unsigned fenc(float f) {
    unsigned u = __float_as_uint(f); return (u & 0x80000000u) ? ~u : (u | 0x80000000u);
}
__device__ __forceinline__ float fdec(unsigned u) {
    u = (u & 0x80000000u) ? (u & 0x7fffffffu) : ~u; return __uint_as_float(u);
}
__device__ __forceinline__ float warp_min(float v) {
    #pragma unroll
    for (int o = 16; o; o >>= 1) v = fminf(v, __shfl_xor_sync(~0u, v, o));
    return v;
}
__device__ __forceinline__ float warp_max(float v) {
    #pragma unroll
    for (int o = 16; o; o >>= 1) v = fmaxf(v, __shfl_xor_sync(~0u, v, o));
    return v;
}
__device__ __forceinline__ void ldmx4(unsigned* r, unsigned addr) {
    asm volatile("ldmatrix.sync.aligned.m8n8.x4.shared.b16 {%0,%1,%2,%3}, [%4];"
                 : "=r"(r[0]), "=r"(r[1]), "=r"(r[2]), "=r"(r[3]) : "r"(addr));
}
__device__ __forceinline__ void mma_f16(float* c, const unsigned* a, unsigned b0, unsigned b1) {
    asm volatile("mma.sync.aligned.m16n8k16.row.col.f32.f16.f16.f32 "
                 "{%0,%1,%2,%3}, {%4,%5,%6,%7}, {%8,%9}, {%0,%1,%2,%3};"
                 : "+f"(c[0]), "+f"(c[1]), "+f"(c[2]), "+f"(c[3])
                 : "r"(a[0]), "r"(a[1]), "r"(a[2]), "r"(a[3]), "r"(b0), "r"(b1));
}

// ---------------- fused prep + bandwidth phase 1 ----------------
__global__ void k_prepbw(const float* __restrict__ x, const float* __restrict__ tx,
                         const float* __restrict__ tr, int m, int n) {
    __shared__ double sds[8][8][4], sds2[8][8][4];
    const int tid = threadIdx.x;
    if (blockIdx.x < BWB) {
        const int b = blockIdx.x;
        const float4* tx4 = (const float4*)tx;
        double s[4] = {0,0,0,0}, s2[4] = {0,0,0,0};
        #pragma unroll
        for (int it = 0; it < 4; it++) {
            float4 v = tx4[(size_t)(b * 128 + it * 32) * 8 + tid];
            double vx = v.x, vy = v.y, vz = v.z, vw = v.w;
            s[0] += vx; s2[0] += vx*vx; s[1] += vy; s2[1] += vy*vy;
            s[2] += vz; s2[2] += vz*vz; s[3] += vw; s2[3] += vw*vw;
        }
        #pragma unroll
        for (int o = 8; o <= 16; o <<= 1)
            #pragma unroll
            for (int k = 0; k < 4; k++) {
                s[k]  += __shfl_xor_sync(~0u, s[k],  o);
                s2[k] += __shfl_xor_sync(~0u, s2[k], o);
            }
        int w = tid >> 5, l = tid & 31;
        if (l < 8)
            #pragma unroll
            for (int k = 0; k < 4; k++) { sds[w][l][k] = s[k]; sds2[w][l][k] = s2[k]; }
        __syncthreads();
        if (tid < 8)
            #pragma unroll
            for (int k = 0; k < 4; k++) {
                double a = 0, a2 = 0;
                #pragma unroll
                for (int ww = 0; ww < 8; ww++) { a += sds[ww][tid][k]; a2 += sds2[ww][tid][k]; }
                g_bws[b * D + tid * 4 + k] = a; g_bws2[b * D + tid * 4 + k] = a2;
            }
        return;
    }
    int idx = (blockIdx.x - BWB) * 256 + tid;
    int row = idx >> 3, g = idx & 7;
    const bool isq = (row < m);
    int r2 = isq ? row : row - m;
    const float4* src = isq ? (const float4*)x : (const float4*)tx;
    float4 v = src[(size_t)r2 * 8 + g];
    __half hx = __float2half_rn(v.x), hy = __float2half_rn(v.y);
    __half hz = __float2half_rn(v.z), hw = __float2half_rn(v.w);
    float qx = __half2float(hx), qy = __half2float(hy);
    float qz = __half2float(hz), qw = __half2float(hw);
    float s = fmaf(qx, qx, fmaf(qy, qy, fmaf(qz, qz, qw * qw)));
    s += __shfl_xor_sync(~0u, s, 1);
    s += __shfl_xor_sync(~0u, s, 2);
    s += __shfl_xor_sync(~0u, s, 4);
    uint2 hi;
    hi.x = (unsigned)__half_as_ushort(hx) | ((unsigned)__half_as_ushort(hy) << 16);
    hi.y = (unsigned)__half_as_ushort(hz) | ((unsigned)__half_as_ushort(hw) << 16);
    if (isq) {
        ((uint2*)g_Ah)[(size_t)r2 * 8 + g] = hi;
        if (g == 0) g_qe[r2] = s;
    } else {
        ((uint2*)g_Bh)[(size_t)r2 * 8 + g] = hi;
        if (g == 0) {
            float* e = (float*)&g_ext4[r2 >> 1];
            if (r2 & 1) { e[1] = s; e[3] = tr[r2]; }
            else        { e[0] = s; e[2] = tr[r2]; }
        }
    }
}

// ---------------- bandwidth phase 2 + scalar init ----------------
__global__ void k_bw2(int n) {
    int d = threadIdx.x;
    double s = 0, s2 = 0;
    for (int b = 0; b < BWB; b++) { s += g_bws[b * D + d]; s2 += g_bws2[b * D + d]; }
    double mean = s / n, var = (s2 - n * mean * mean) / (n - 1);
    double sd = sqrt(var > 0.0 ? var : 0.0);
    #pragma unroll
    for (int o = 16; o; o >>= 1) sd += __shfl_xor_sync(~0u, sd, o);
    if (d == 0) {
        double bw = (sd / D) * exp(-log((double)n) / (D + 4));
        g_cl = (float)(1.0 / (2.0 * bw * bw) * 1.4426950408889634);
        g_rmin = ~0u; g_rmax = 0u; g_smin = ~0u; g_smax = 0u;
        g_cnt = 0u;
    }
}

// ---------------- HMMA KDE mainloop: 4 warps x 32 queries, occ 8 ----------------
__device__ __forceinline__ void load_tile(unsigned sb, int g, int b, int tid) {
    unsigned base = sb + b * BUFSZ;
    const __half* sh = g_Bh + (size_t)g * NTT * D;
    #pragma unroll
    for (int i = 0; i < 4; i++) {
        int idx = tid + i * 128, row = idx >> 2, c = idx & 3;
        cp16(base + row * PITCH + c * 16, sh + row * D + c * 8);
    }
    if (tid < 64) cp16(base + OFFEXT + tid * 16, g_ext4 + (size_t)g * 64 + tid);
    asm volatile("cp.async.commit_group;" ::: "memory");
}

__global__ void __launch_bounds__(128, 8)
k_main_mma(int n) {
    __shared__ __align__(16) char smem[SMEMSZ];
    unsigned sb = (unsigned)__cvta_generic_to_shared(smem);
    const int tid = threadIdx.x, w = tid >> 5, lane = tid & 31;
    const int qblk  = blockIdx.x & 127;
    const int split = blockIdx.x >> 7;               // 0..8, grid = 1152
    const int NTtot = n / NTT;                       // 64
    const int tb_lo = (split * NTtot) / TSMAX;
    const int tb_hi = ((split + 1) * NTtot) / TSMAX;

    // ---- stage A (128 rows, pitch 80) at sb, extract frags, reuse smem ----
    #pragma unroll
    for (int i = 0; i < 4; i++) {
        int idx = tid + i * 128, row = idx >> 2, c = idx & 3;
        cp16(sb + row * PITCH + c * 16, g_Ah + (size_t)(qblk * MQ + row) * D + c * 8);
    }
    asm volatile("cp.async.commit_group;" ::: "memory");
    asm volatile("cp.async.wait_group 0;" ::: "memory");
    __syncthreads();

    unsigned ah0[2][4], ah1[2][4];                   // warp owns rows w*32..w*32+31
    {
        unsigned rowsel = lane & 15, colb = (lane >> 4) * 16;
        unsigned ab0 = sb + (w * 32 + rowsel) * PITCH + colb;
        unsigned ab1 = ab0 + 16 * PITCH;
        ldmx4(ah0[0], ab0);
        ldmx4(ah0[1], ab0 + 32);
        ldmx4(ah1[0], ab1);
        ldmx4(ah1[1], ab1 + 32);
    }
    const int qg = lane >> 2;
    const float cl = g_cl;
    const unsigned long long negcl2 = dup2(-cl);
    const unsigned long long K2d    = dup2(cl + cl);
    const int qbase = qblk * MQ + w * 32;
    const unsigned long long cqa0 = dup2(-cl * g_qe[qbase + qg]);
    const unsigned long long cqb0 = dup2(-cl * g_qe[qbase + qg + 8]);
    const unsigned long long cqa1 = dup2(-cl * g_qe[qbase + qg + 16]);
    const unsigned long long cqb1 = dup2(-cl * g_qe[qbase + qg + 24]);
    __syncthreads();

    load_tile(sb, tb_lo, 0, tid);

    float na0 = 0.f, da0 = 0.f, nb0 = 0.f, db0 = 0.f;
    float na1 = 0.f, da1 = 0.f, nb1 = 0.f, db1 = 0.f;

    const unsigned browAdd = (lane >> 4) * 8 + (lane & 7);
    const unsigned bcolb   = ((lane >> 3) & 1) * 16;

    for (int tb = tb_lo; tb < tb_hi; tb++) {
        const int buf = (tb - tb_lo) & 1;
        if (tb + 1 < tb_hi) {
            load_tile(sb, tb + 1, buf ^ 1, tid);
            asm volatile("cp.async.wait_group 1;" ::: "memory");
        } else {
            asm volatile("cp.async.wait_group 0;" ::: "memory");
        }
        __syncthreads();

        const unsigned bbase = sb + buf * BUFSZ;
        const float4* ext = (const float4*)(smem + buf * BUFSZ + OFFEXT);

        #pragma unroll
        for (int np = 0; np < 8; np++) {
            const unsigned rb = bbase + (np * 16 + browAdd) * PITCH + bcolb;
            float c0[2][4], c1[2][4];
            #pragma unroll
            for (int s = 0; s < 2; s++)
                #pragma unroll
                for (int k = 0; k < 4; k++) { c0[s][k] = 0.f; c1[s][k] = 0.f; }

            #pragma unroll
            for (int ks = 0; ks < 2; ks++) {
                unsigned bv[4];
                ldmx4(bv, rb + ks * 32);
                mma_f16(c0[0], ah0[ks], bv[0], bv[1]);
                mma_f16(c0[1], ah0[ks], bv[2], bv[3]);
                mma_f16(c1[0], ah1[ks], bv[0], bv[1]);
                mma_f16(c1[1], ah1[ks], bv[2], bv[3]);
            }

            #pragma unroll
            for (int ns = 0; ns < 2; ns++) {
                float4 e = ext[(np * 2 + ns) * 4 + (lane & 3)];
                unsigned long long t2p = pack2(e.x, e.y);
                unsigned long long ba0 = fma2(t2p, negcl2, cqa0);
                unsigned long long bb0 = fma2(t2p, negcl2, cqb0);
                unsigned long long ba1 = fma2(t2p, negcl2, cqa1);
                unsigned long long bb1 = fma2(t2p, negcl2, cqb1);
                unsigned long long pa0 = fma2(pack2(c0[ns][0], c0[ns][1]), K2d, ba0);
                unsigned long long pb0 = fma2(pack2(c0[ns][2], c0[ns][3]), K2d, bb0);
                unsigned long long pa1 = fma2(pack2(c1[ns][0], c1[ns][1]), K2d, ba1);
                unsigned long long pb1 = fma2(pack2(c1[ns][2], c1[ns][3]), K2d, bb1);
                float2 f0 = unpack2(pa0), f1 = unpack2(pb0);
                float2 f2 = unpack2(pa1), f3 = unpack2(pb1);
                float w0 = ex2f(f0.x), w1 = ex2f(f0.y);
                float w2 = ex2f(f1.x), w3 = ex2f(f1.y);
                float w4 = ex2f(f2.x), w5 = ex2f(f2.y);
                float w6 = ex2f(f3.x), w7 = ex2f(f3.y);
                na0 = fmaf(w0, e.z, na0); na0 = fmaf(w1, e.w, na0); da0 += w0 + w1;
                nb0 = fmaf(w2, e.z, nb0); nb0 = fmaf(w3, e.w, nb0); db0 += w2 + w3;
                na1 = fmaf(w4, e.z, na1); na1 = fmaf(w5, e.w, na1); da1 += w4 + w5;
                nb1 = fmaf(w6, e.z, nb1); nb1 = fmaf(w7, e.w, nb1); db1 += w6 + w7;
            }
        }
        __syncthreads();
    }

    #pragma unroll
    for (int o = 1; o <= 2; o <<= 1) {
        na0 += __shfl_xor_sync(~0u, na0, o); da0 += __shfl_xor_sync(~0u, da0, o);
        nb0 += __shfl_xor_sync(~0u, nb0, o); db0 += __shfl_xor_sync(~0u, db0, o);
        na1 += __shfl_xor_sync(~0u, na1, o); da1 += __shfl_xor_sync(~0u, da1, o);
        nb1 += __shfl_xor_sync(~0u, nb1, o); db1 += __shfl_xor_sync(~0u, db1, o);
    }
    if ((lane & 3) == 0) {
        int q = qbase + qg;
        g_pnum[split][q]      = na0; g_pden[split][q]      = da0;
        g_pnum[split][q + 8]  = nb0; g_pden[split][q + 8]  = db0;
        g_pnum[split][q + 16] = na1; g_pden[split][q + 16] = da1;
        g_pnum[split][q + 24] = nb1; g_pden[split][q + 24] = db1;
    }
}

// ---------------- fused reduce + final (device-wide arrival barrier) ----------------
__global__ void k_redfin(const float* __restrict__ sig, float* __restrict__ out, int m) {
    __shared__ float s_rmin[8], s_rmax[8], s_smin[8], s_smax[8];
    int q = blockIdx.x * blockDim.x + threadIdx.x;
    float rx = 0.f, sg = 0.f;
    float rmn = 3.4e38f, rmx = -3.4e38f, smn = 3.4e38f, smx = -3.4e38f;
    if (q < m) {
        float num = 0.f, den = 0.f;
        #pragma unroll
        for (int s = 0; s < TSMAX; s++) { num += g_pnum[s][q]; den += g_pden[s][q]; }
        rx = num / (den + EPSV);
        sg = sig[q];
        rmn = rx; rmx = rx; smn = sg; smx = sg;
    }
    float wr0 = warp_min(rmn), wr1 = warp_max(rmx), ws0 = warp_min(smn), ws1 = warp_max(smx);
    int w = threadIdx.x >> 5, l = threadIdx.x & 31, nw = blockDim.x >> 5;
    if (l == 0) { s_rmin[w] = wr0; s_rmax[w] = wr1; s_smin[w] = ws0; s_smax[w] = ws1; }
    __syncthreads();
    if (threadIdx.x == 0) {
        float a = s_rmin[0], b = s_rmax[0], cc = s_smin[0], d = s_smax[0];
        for (int i = 1; i < nw; i++) {
            a = fminf(a, s_rmin[i]); b = fmaxf(b, s_rmax[i]);
            cc = fminf(cc, s_smin[i]); d = fmaxf(d, s_smax[i]);
        }
        atomicMin(&g_rmin, fenc(a)); atomicMax(&g_rmax, fenc(b));
        atomicMin(&g_smin, fenc(cc)); atomicMax(&g_smax, fenc(d));
        __threadfence();
        atomicAdd(&g_cnt, 1u);
        while (atomicAdd(&g_cnt, 0u) < gridDim.x) { }
    }
    __syncthreads();
    if (q >= m) return;
    float t1 = 0.5f * (rx - fdec(g_rmin)) / (fdec(g_rmax) - fdec(g_rmin) + EPSV);
    float t2 = 0.5f * (sg - fdec(g_smin)) / (fdec(g_smax) - fdec(g_smin) + EPSV);
    out[q] = t1 + t2;
}

// ---------------- launch ----------------
extern "C" void kernel_launch(void* const* d_in, const int* in_sizes, int n_in,
                              void* d_out, int out_size) {
    const float* x   = (const float*)d_in[0];
    const float* tx  = (const float*)d_in[1];
    const float* tr  = (const float*)d_in[2];
    const float* sig = (const float*)d_in[3];
    int m = in_sizes[0] / D;   // 16384
    int n = in_sizes[1] / D;   // 8192

    k_prepbw<<<BWB + (m + n) * 8 / 256, 256>>>(x, tx, tr, m, n);
    k_bw2<<<1, 32>>>(n);
    k_main_mma<<<128 * TSMAX, 128>>>(n);
    k_redfin<<<(m + 255) / 256, 256>>>(sig, (float*)d_out, m);
}